// round 15
// baseline (speedup 1.0000x reference)
#include <cuda_runtime.h>
#include <cuda_bf16.h>
#include <cstdint>

// ---------------- problem constants ----------------
#define BATCH 32
#define N1 4096
#define S1 512
#define G1 32
#define S2 128
#define G2 64

// ---------------- scratch (device globals; no cudaMalloc allowed) ----------------
__device__ float g_bufA[44u * 1024u * 1024u];
__device__ float g_bufB[36u * 1024u * 1024u];
__device__ float g_cent1[BATCH * S1 * 3];
__device__ float g_cent2[BATCH * S2 * 3];
__device__ int   g_idx1[BATCH * S1];
__device__ int   g_gidx2[BATCH * S2 * G2];
__device__ float g_l1p[BATCH * S1 * 128];
__device__ float g_l2p[BATCH * S2 * 256];
__device__ float g_feat[BATCH * 1024];
__device__ uint32_t g_wpk[1024u * 1024u];   // packed split-bf16 weights (4MB)

// packed-weight offsets (words)
#define WO_S1W1 0        // 64 x 64
#define WO_S1W2 4096     // 128 x 64
#define WO_S2W1 32768    // 128 x 128
#define WO_S2W2 49152    // 256 x 128
#define WO_S3W0 81920    // 256 x 288 (K=259)
#define WO_S3W1 155648   // 512 x 256
#define WO_S3W2 286720   // 1024 x 512
#define WO_FPW  811008   // 128 x 128 (cols 3..130 of s2w0)

// FP (unique-point feature projection) buffer: inside g_bufB at float offset 16M
#define FP_OFFSET (16u * 1024u * 1024u)

// squared distance with NO fma contraction, same assoc order as jnp.sum over last axis
__device__ __forceinline__ float sqd(float dx, float dy, float dz) {
    return __fadd_rn(__fadd_rn(__fmul_rn(dx, dx), __fmul_rn(dy, dy)), __fmul_rn(dz, dz));
}

// ================= mma.sync helpers =================
__device__ __forceinline__ uint32_t smem_u32(const void* p) {
    uint32_t a;
    asm("{ .reg .u64 t; cvta.to.shared.u64 t, %1; cvt.u32.u64 %0, t; }" : "=r"(a) : "l"(p));
    return a;
}
__device__ __forceinline__ void ldm_x4(uint32_t addr, uint32_t& r0, uint32_t& r1,
                                       uint32_t& r2, uint32_t& r3) {
    asm volatile("ldmatrix.sync.aligned.m8n8.x4.shared.b16 {%0,%1,%2,%3}, [%4];"
                 : "=r"(r0), "=r"(r1), "=r"(r2), "=r"(r3) : "r"(addr));
}
__device__ __forceinline__ void mma_bf16(float* c, uint32_t a0, uint32_t a1, uint32_t a2,
                                         uint32_t a3, uint32_t b0, uint32_t b1) {
    asm volatile("mma.sync.aligned.m16n8k16.row.col.f32.bf16.bf16.f32 "
                 "{%0,%1,%2,%3}, {%4,%5,%6,%7}, {%8,%9}, {%0,%1,%2,%3};"
                 : "+f"(c[0]), "+f"(c[1]), "+f"(c[2]), "+f"(c[3])
                 : "r"(a0), "r"(a1), "r"(a2), "r"(a3), "r"(b0), "r"(b1));
}
__device__ __forceinline__ uint32_t pack_hi(float v0, float v1, float& rl0, float& rl1) {
    __nv_bfloat16 h0 = __float2bfloat16(v0);
    __nv_bfloat16 h1 = __float2bfloat16(v1);
    rl0 = v0 - __bfloat162float(h0);
    rl1 = v1 - __bfloat162float(h1);
    return ((uint32_t)__bfloat16_as_ushort(h1) << 16) | (uint32_t)__bfloat16_as_ushort(h0);
}
__device__ __forceinline__ uint32_t pack_lo(float l0, float l1) {
    return ((uint32_t)__bfloat16_as_ushort(__float2bfloat16(l1)) << 16) |
           (uint32_t)__bfloat16_as_ushort(__float2bfloat16(l0));
}
__device__ __forceinline__ uint32_t packv(float v) {
    __nv_bfloat16 h = __float2bfloat16(v);
    float l = v - __bfloat162float(h);
    return ((uint32_t)__bfloat16_as_ushort(__float2bfloat16(l)) << 16) |
           (uint32_t)__bfloat16_as_ushort(h);
}

// ---------------- merged weight pre-pack (one launch) ----------------
struct PkSeg { const float* src; int dst; int Kp; int srcK; int colOff; int Kcopy; };
struct PkTab { PkSeg s[8]; int cum[9]; };

__global__ void prepack_all(PkTab tab, uint32_t* __restrict__ out) {
    int idx = blockIdx.x * blockDim.x + threadIdx.x;
    if (idx >= tab.cum[8]) return;
    int si = 0;
    while (idx >= tab.cum[si + 1]) si++;
    int loc = idx - tab.cum[si];
    PkSeg sg = tab.s[si];
    int r = loc / sg.Kp, c = loc - r * sg.Kp;
    float v = (c < sg.Kcopy) ? sg.src[(size_t)r * sg.srcK + sg.colOff + c] : 0.0f;
    out[sg.dst + loc] = packv(v);
}

// ======================================================================
// One MMA layer over a 128-row smem-resident input tile.
// 512 threads, 4x4 warps, warp tile 32x16.  out = relu(in @ W^T + bias).
// ======================================================================
template <int POOLG, int OUT_SMEM, int OUT_PACKED>
__device__ __forceinline__ void mma_layer(
    const __nv_bfloat16* sInH, const __nv_bfloat16* sInL, int ldaeIn, int Kp,
    const uint32_t* __restrict__ Wp, int Kw, const float* __restrict__ bias, int N,
    __nv_bfloat16* sOutH, __nv_bfloat16* sOutL, int ldaeOut,
    void* Cv, int bm,
    __nv_bfloat16 (*sWh)[40], __nv_bfloat16 (*sWl)[40], float* pool) {
    const int tid = threadIdx.x;
    const int lane = tid & 31;
    const int wid = tid >> 5;
    const int warp_m = wid & 3;
    const int warp_n = wid >> 2;

    const uint32_t aInH = smem_u32(sInH);
    const uint32_t aInL = smem_u32(sInL);
    const uint32_t aWh = smem_u32(&sWh[0][0]);
    const uint32_t aWl = smem_u32(&sWl[0][0]);
    const int a_r = warp_m * 32 + (lane & 15);
    const int a_c = (lane >> 4) << 3;
    const int b_r = warp_n * 16 + ((lane >> 4) << 3) + (lane & 7);
    const int b_c = ((lane >> 3) & 1) << 3;
    const uint32_t baseAh = aInH + (uint32_t)(a_r * ldaeIn + a_c) * 2;
    const uint32_t baseAl = aInL + (uint32_t)(a_r * ldaeIn + a_c) * 2;
    const uint32_t stepT = (uint32_t)(16 * ldaeIn * 2);
    const uint32_t baseWh = aWh + (uint32_t)(b_r * 40 + b_c) * 2;
    const uint32_t baseWl = aWl + (uint32_t)(b_r * 40 + b_c) * 2;

    const int nch = Kp >> 5;
    const int g = lane >> 2;
    const int cpair = (lane & 3) << 1;

    for (int nb = 0; nb < (N >> 6); nb++) {
        const int bn = nb << 6;
        float acc[2][2][4];
#pragma unroll
        for (int t = 0; t < 2; t++)
#pragma unroll
            for (int u = 0; u < 2; u++)
#pragma unroll
                for (int i = 0; i < 4; i++) acc[t][u][i] = 0.0f;

        for (int kc = 0; kc < nch; kc++) {
            const int k0 = kc << 5;
            // ---- fill W tiles from packed: 64 rows x 32 words, 1 uint4/thread ----
            {
                int r = tid >> 3, q = tid & 7;
                uint4 v = *(const uint4*)(Wp + (size_t)(bn + r) * Kw + k0 + q * 4);
                uint32_t h01 = __byte_perm(v.x, v.y, 0x5410);
                uint32_t l01 = __byte_perm(v.x, v.y, 0x7632);
                uint32_t h23 = __byte_perm(v.z, v.w, 0x5410);
                uint32_t l23 = __byte_perm(v.z, v.w, 0x7632);
                *(uint2*)&sWh[r][q * 4] = make_uint2(h01, h23);
                *(uint2*)&sWl[r][q * 4] = make_uint2(l01, l23);
            }
            __syncthreads();

#pragma unroll
            for (int ks = 0; ks < 2; ks++) {
                const uint32_t koffA = (uint32_t)((k0 + (ks << 4)) * 2);
                const uint32_t koffW = (uint32_t)((ks << 4) * 2);
                uint32_t ah[2][4], al[2][4];
#pragma unroll
                for (int t = 0; t < 2; t++) {
                    ldm_x4(baseAh + t * stepT + koffA, ah[t][0], ah[t][1], ah[t][2], ah[t][3]);
                    ldm_x4(baseAl + t * stepT + koffA, al[t][0], al[t][1], al[t][2], al[t][3]);
                }
                uint32_t bh[4], bl[4];
                ldm_x4(baseWh + koffW, bh[0], bh[1], bh[2], bh[3]);
                ldm_x4(baseWl + koffW, bl[0], bl[1], bl[2], bl[3]);
#pragma unroll
                for (int t = 0; t < 2; t++)
#pragma unroll
                    for (int u = 0; u < 2; u++) {
                        mma_bf16(acc[t][u], ah[t][0], ah[t][1], ah[t][2], ah[t][3], bh[2 * u], bh[2 * u + 1]);
                        mma_bf16(acc[t][u], ah[t][0], ah[t][1], ah[t][2], ah[t][3], bl[2 * u], bl[2 * u + 1]);
                        mma_bf16(acc[t][u], al[t][0], al[t][1], al[t][2], al[t][3], bh[2 * u], bh[2 * u + 1]);
                    }
            }
            __syncthreads();
        }

        if (POOLG == 0) {
#pragma unroll
            for (int t = 0; t < 2; t++) {
#pragma unroll
                for (int u = 0; u < 2; u++) {
                    int col = bn + warp_n * 16 + u * 8 + cpair;
                    float b0 = bias[col], b1 = bias[col + 1];
                    float v00 = fmaxf(acc[t][u][0] + b0, 0.0f);
                    float v01 = fmaxf(acc[t][u][1] + b1, 0.0f);
                    float v10 = fmaxf(acc[t][u][2] + b0, 0.0f);
                    float v11 = fmaxf(acc[t][u][3] + b1, 0.0f);
                    if (OUT_SMEM) {
                        int r0 = warp_m * 32 + t * 16 + g;
                        float l0, l1;
                        uint32_t h0w = pack_hi(v00, v01, l0, l1);
                        uint32_t l0w = pack_lo(l0, l1);
                        *(uint32_t*)((uint16_t*)sOutH + (size_t)r0 * ldaeOut + col) = h0w;
                        *(uint32_t*)((uint16_t*)sOutL + (size_t)r0 * ldaeOut + col) = l0w;
                        uint32_t h1w = pack_hi(v10, v11, l0, l1);
                        uint32_t l1w = pack_lo(l0, l1);
                        *(uint32_t*)((uint16_t*)sOutH + (size_t)(r0 + 8) * ldaeOut + col) = h1w;
                        *(uint32_t*)((uint16_t*)sOutL + (size_t)(r0 + 8) * ldaeOut + col) = l1w;
                    } else {
                        int r0 = bm + warp_m * 32 + t * 16 + g;
                        if (OUT_PACKED) {
                            uint32_t* C = (uint32_t*)Cv;
                            *(uint2*)(C + (size_t)r0 * N + col) = make_uint2(packv(v00), packv(v01));
                            *(uint2*)(C + (size_t)(r0 + 8) * N + col) = make_uint2(packv(v10), packv(v11));
                        } else {
                            float* C = (float*)Cv;
                            *(float2*)(C + (size_t)r0 * N + col) = make_float2(v00, v01);
                            *(float2*)(C + (size_t)(r0 + 8) * N + col) = make_float2(v10, v11);
                        }
                    }
                }
            }
        } else {
#pragma unroll
            for (int u = 0; u < 2; u++) {
                int col = bn + warp_n * 16 + u * 8 + cpair;
                float b0 = bias[col], b1 = bias[col + 1];
                float m0 = fmaxf(fmaxf(acc[0][u][0], acc[0][u][2]), fmaxf(acc[1][u][0], acc[1][u][2]));
                float m1 = fmaxf(fmaxf(acc[0][u][1], acc[0][u][3]), fmaxf(acc[1][u][1], acc[1][u][3]));
#pragma unroll
                for (int off = 4; off < 32; off <<= 1) {
                    m0 = fmaxf(m0, __shfl_xor_sync(0xffffffffu, m0, off));
                    m1 = fmaxf(m1, __shfl_xor_sync(0xffffffffu, m1, off));
                }
                m0 = fmaxf(m0 + b0, 0.0f);
                m1 = fmaxf(m1 + b1, 0.0f);
                if (POOLG == 32) {
                    if (lane < 4) {
                        int s = bm / 32 + warp_m;
                        uint32_t* C = (uint32_t*)Cv;
                        *(uint2*)(C + (size_t)s * N + col) = make_uint2(packv(m0), packv(m1));
                    }
                } else {
                    if (lane < 4) {
                        int lc = warp_n * 16 + u * 8 + cpair;
                        pool[warp_m * 64 + lc] = m0;
                        pool[warp_m * 64 + lc + 1] = m1;
                    }
                }
            }
            if (POOLG == 64) {
                __syncthreads();
                if (tid < 128) {
                    int gg = tid >> 6, c = tid & 63;
                    float v = fmaxf(pool[2 * gg * 64 + c], pool[(2 * gg + 1) * 64 + c]);
                    ((uint32_t*)Cv)[(size_t)(bm / 64 + gg) * N + bn + c] = packv(v);
                }
                __syncthreads();
            }
        }
    }
    __syncthreads();
}

// ======================================================================
// SA1 fused: L0 gen (3->64) -> L1 (64->64) -> L2 (64->128) + pool32
// ======================================================================
#define SA1_SMEM 88064
__global__ __launch_bounds__(512, 2)
void sa1_fused(const float* __restrict__ GXYZ,
               const float* __restrict__ W0, const float* __restrict__ B0,
               const uint32_t* __restrict__ W1p, const float* __restrict__ b1,
               const uint32_t* __restrict__ W2p, const float* __restrict__ b2,
               uint32_t* __restrict__ l1p) {
    extern __shared__ char smem[];
    __nv_bfloat16* t0H = (__nv_bfloat16*)(smem);
    __nv_bfloat16* t0L = (__nv_bfloat16*)(smem + 18432);
    __nv_bfloat16* t1H = (__nv_bfloat16*)(smem + 36864);
    __nv_bfloat16* t1L = (__nv_bfloat16*)(smem + 55296);
    __nv_bfloat16 (*sWh)[40] = (__nv_bfloat16(*)[40])(smem + 73728);
    __nv_bfloat16 (*sWl)[40] = (__nv_bfloat16(*)[40])(smem + 78848);
    float* pool = (float*)(smem + 83968);
    float* sxyz = (float*)(smem + 84992);
    float* sW0 = sxyz + 512;
    float* sB0 = sW0 + 192;

    const int tid = threadIdx.x;
    const int bm = blockIdx.x * 128;
    const int ldae = 72;

    if (tid < 192) sW0[tid] = W0[tid];
    if (tid >= 192 && tid < 256) sB0[tid - 192] = B0[tid - 192];
    if (tid >= 256 && tid < 384) {
        int r = tid - 256;
        const float* g = GXYZ + (size_t)(bm + r) * 3;
        sxyz[r * 4] = g[0]; sxyz[r * 4 + 1] = g[1]; sxyz[r * 4 + 2] = g[2];
    }
    __syncthreads();
#pragma unroll
    for (int i = 0; i < 8; i++) {
        int idx = (i << 9) + tid;
        int r = idx >> 5;
        int pc = (idx & 31) << 1;
        float x = sxyz[r * 4], y = sxyz[r * 4 + 1], z = sxyz[r * 4 + 2];
        float v0 = fmaxf(sB0[pc] + x * sW0[pc * 3] + y * sW0[pc * 3 + 1] + z * sW0[pc * 3 + 2], 0.0f);
        float v1 = fmaxf(sB0[pc + 1] + x * sW0[pc * 3 + 3] + y * sW0[pc * 3 + 4] + z * sW0[pc * 3 + 5], 0.0f);
        float l0, l1;
        uint32_t ph = pack_hi(v0, v1, l0, l1);
        *(uint32_t*)&t0H[r * ldae + pc] = ph;
        *(uint32_t*)&t0L[r * ldae + pc] = pack_lo(l0, l1);
    }
    __syncthreads();

    mma_layer<0, 1, 0>(t0H, t0L, 72, 64, W1p, 64, b1, 64,
                       t1H, t1L, 72, nullptr, bm, sWh, sWl, pool);
    mma_layer<32, 0, 1>(t1H, t1L, 72, 64, W2p, 64, b2, 128,
                        nullptr, nullptr, 0, l1p, bm, sWh, sWl, pool);
}

// ======================================================================
// SA2 fused (deduped L1): fill t1 = relu(FP[i] + b1 + W1xyz . xyz_rel)
//   -> L2 (128->128) -> L3 (128->256)+pool64
// ======================================================================
#define SA2_SMEM 152576
__global__ __launch_bounds__(512)
void sa2_fused(const int* __restrict__ gidx,
               const float* __restrict__ cent1, const float* __restrict__ cent2,
               const float* __restrict__ FP,
               const float* __restrict__ W0src, const float* __restrict__ b1,
               const uint32_t* __restrict__ W2p, const float* __restrict__ b2,
               const uint32_t* __restrict__ W3p, const float* __restrict__ b3,
               uint32_t* __restrict__ l2p) {
    extern __shared__ char smem[];
    __nv_bfloat16* t1H = (__nv_bfloat16*)(smem);
    __nv_bfloat16* t1L = (__nv_bfloat16*)(smem + 34816);
    __nv_bfloat16* t2H = (__nv_bfloat16*)(smem + 69632);
    __nv_bfloat16* t2L = (__nv_bfloat16*)(smem + 104448);
    __nv_bfloat16 (*sWh)[40] = (__nv_bfloat16(*)[40])(smem + 139264);
    __nv_bfloat16 (*sWl)[40] = (__nv_bfloat16(*)[40])(smem + 144384);
    float* pool = (float*)(smem + 149504);
    float* wx = (float*)(smem + 150528);
    float* wy = (float*)(smem + 151040);
    float* wz = (float*)(smem + 151552);
    float* sb1 = (float*)(smem + 152064);

    const int tid = threadIdx.x;
    const int bm = blockIdx.x * 128;

    if (tid < 128) {
        wx[tid] = W0src[tid * 131];
        wy[tid] = W0src[tid * 131 + 1];
        wz[tid] = W0src[tid * 131 + 2];
        sb1[tid] = b1[tid];
    }
    __syncthreads();

    // ---- fill t1 directly: relu(FPfeat + bias + xyz part), pack hi/lo ----
    {
        const int r = tid >> 2, q = tid & 3;
        const int gr = bm + r;
        const int bs = gr >> 6;
        const int n = gr & 63;
        const int b = bs >> 7;
        const int i = gidx[(size_t)bs * 64 + n];
        const float* p1 = cent1 + ((size_t)b * 512 + i) * 3;
        const float* p2 = cent2 + (size_t)bs * 3;
        float dx = p1[0] - p2[0], dy = p1[1] - p2[1], dz = p1[2] - p2[2];
        const float* fprow = FP + ((size_t)b * 512 + i) * 128;
        uint16_t* dh = (uint16_t*)t1H + (size_t)r * 136;
        uint16_t* dl = (uint16_t*)t1L + (size_t)r * 136;
        const int c0 = q * 32;
#pragma unroll
        for (int c = c0; c < c0 + 32; c += 2) {
            float v0 = fmaxf(fprow[c] + sb1[c] + wx[c] * dx + wy[c] * dy + wz[c] * dz, 0.0f);
            float v1 = fmaxf(fprow[c + 1] + sb1[c + 1] + wx[c + 1] * dx + wy[c + 1] * dy + wz[c + 1] * dz, 0.0f);
            float l0, l1;
            uint32_t hw = pack_hi(v0, v1, l0, l1);
            *(uint32_t*)(dh + c) = hw;
            *(uint32_t*)(dl + c) = pack_lo(l0, l1);
        }
    }
    __syncthreads();

    mma_layer<0, 1, 0>(t1H, t1L, 136, 128, W2p, 128, b2, 128,
                       t2H, t2L, 136, nullptr, bm, sWh, sWl, pool);
    mma_layer<64, 0, 1>(t2H, t2L, 136, 128, W3p, 128, b3, 256,
                        nullptr, nullptr, 0, l2p, bm, sWh, sWl, pool);
}

// ======================================================================
// STREAMING GEMM, 512 threads, packed A and packed W.
// DOBR: 1 = add bias + relu; 0 = raw accumulation output (fp32 only).
// ======================================================================
#define LDA 40
template <int POOLG, int OUT_PACKED, int DOBR>
__global__ __launch_bounds__(512, 2)
void gemm_str(const uint32_t* __restrict__ A, const uint32_t* __restrict__ Wp,
              const float* __restrict__ bias, void* __restrict__ Cv,
              int M, int Kw, int Kp, int N) {
    __shared__ __nv_bfloat16 sAh[128][LDA];
    __shared__ __nv_bfloat16 sAl[128][LDA];
    __shared__ __nv_bfloat16 sWh[64][LDA];
    __shared__ __nv_bfloat16 sWl[64][LDA];
    __shared__ float pool[4][64];

    const int tid = threadIdx.x;
    const int lane = tid & 31;
    const int wid = tid >> 5;
    const int warp_m = wid & 3;
    const int warp_n = wid >> 2;
    const int bm = blockIdx.x * 128, bn = blockIdx.y * 64;

    float acc[2][2][4];
#pragma unroll
    for (int t = 0; t < 2; t++)
#pragma unroll
        for (int u = 0; u < 2; u++)
#pragma unroll
            for (int i = 0; i < 4; i++) acc[t][u][i] = 0.0f;

    const uint32_t aAh = smem_u32(&sAh[0][0]);
    const uint32_t aAl = smem_u32(&sAl[0][0]);
    const uint32_t aWh = smem_u32(&sWh[0][0]);
    const uint32_t aWl = smem_u32(&sWl[0][0]);
    const int a_r = warp_m * 32 + (lane & 15);
    const int a_c = (lane >> 4) << 3;
    const int b_r = warp_n * 16 + ((lane >> 4) << 3) + (lane & 7);
    const int b_c = ((lane >> 3) & 1) << 3;
    const uint32_t baseAh = aAh + (uint32_t)(a_r * LDA + a_c) * 2;
    const uint32_t baseAl = aAl + (uint32_t)(a_r * LDA + a_c) * 2;
    const uint32_t baseWh = aWh + (uint32_t)(b_r * LDA + b_c) * 2;
    const uint32_t baseWl = aWl + (uint32_t)(b_r * LDA + b_c) * 2;
    const uint32_t stepT = (uint32_t)(16 * LDA * 2);

    const int nch = Kp >> 5;
    for (int kc = 0; kc < nch; kc++) {
        const int k0 = kc << 5;
        __syncthreads();
        {
            const int r = tid >> 2, q = tid & 3;
            const uint4* arow = (const uint4*)(A + (size_t)(bm + r) * Kp + k0 + q * 8);
            char* dh = (char*)&sAh[r][q * 8];
            char* dl = (char*)&sAl[r][q * 8];
#pragma unroll
            for (int j = 0; j < 2; j++) {
                uint4 v = arow[j];
                uint32_t h01 = __byte_perm(v.x, v.y, 0x5410);
                uint32_t l01 = __byte_perm(v.x, v.y, 0x7632);
                uint32_t h23 = __byte_perm(v.z, v.w, 0x5410);
                uint32_t l23 = __byte_perm(v.z, v.w, 0x7632);
                *(uint2*)(dh + j * 8) = make_uint2(h01, h23);
                *(uint2*)(dl + j * 8) = make_uint2(l01, l23);
            }
        }
        {
            int r = tid >> 3, q = tid & 7;
            uint4 v = *(const uint4*)(Wp + (size_t)(bn + r) * Kw + k0 + q * 4);
            uint32_t h01 = __byte_perm(v.x, v.y, 0x5410);
            uint32_t l01 = __byte_perm(v.x, v.y, 0x7632);
            uint32_t h23 = __byte_perm(v.z, v.w, 0x5410);
            uint32_t l23 = __byte_perm(v.z, v.w, 0x7632);
            *(uint2*)&sWh[r][q * 4] = make_uint2(h01, h23);
            *(uint2*)&sWl[r][q * 4] = make_uint2(l01, l23);
        }
        __syncthreads();

#pragma unroll
        for (int ks = 0; ks < 2; ks++) {
            const uint32_t koff = (uint32_t)((ks << 4) * 2);
            uint32_t ah[2][4], al[2][4];
#pragma unroll
            for (int t = 0; t < 2; t++) {
                ldm_x4(baseAh + t * stepT + koff, ah[t][0], ah[t][1], ah[t][2], ah[t][3]);
                ldm_x4(baseAl + t * stepT + koff, al[t][0], al[t][1], al[t][2], al[t][3]);
            }
            uint32_t bh[4], bl[4];
            ldm_x4(baseWh + koff, bh[0], bh[1], bh[2], bh[3]);
            ldm_x4(baseWl + koff, bl[0], bl[1], bl[2], bl[3]);
#pragma unroll
            for (int t = 0; t < 2; t++)
#pragma unroll
                for (int u = 0; u < 2; u++) {
                    mma_bf16(acc[t][u], ah[t][0], ah[t][1], ah[t][2], ah[t][3], bh[2 * u], bh[2 * u + 1]);
                    mma_bf16(acc[t][u], ah[t][0], ah[t][1], ah[t][2], ah[t][3], bl[2 * u], bl[2 * u + 1]);
                    mma_bf16(acc[t][u], al[t][0], al[t][1], al[t][2], al[t][3], bh[2 * u], bh[2 * u + 1]);
                }
        }
    }

    const int g = lane >> 2;
    const int cpair = (lane & 3) << 1;
    if (POOLG == 0) {
#pragma unroll
        for (int t = 0; t < 2; t++) {
#pragma unroll
            for (int u = 0; u < 2; u++) {
                int col = bn + warp_n * 16 + u * 8 + cpair;
                float v00 = acc[t][u][0], v01 = acc[t][u][1];
                float v10 = acc[t][u][2], v11 = acc[t][u][3];
                if (DOBR) {
                    float b0 = bias[col], b1 = bias[col + 1];
                    v00 = fmaxf(v00 + b0, 0.0f); v01 = fmaxf(v01 + b1, 0.0f);
                    v10 = fmaxf(v10 + b0, 0.0f); v11 = fmaxf(v11 + b1, 0.0f);
                }
                int r0 = bm + warp_m * 32 + t * 16 + g;
                if (OUT_PACKED) {
                    uint32_t* C = (uint32_t*)Cv;
                    *(uint2*)(C + (size_t)r0 * N + col) = make_uint2(packv(v00), packv(v01));
                    *(uint2*)(C + (size_t)(r0 + 8) * N + col) = make_uint2(packv(v10), packv(v11));
                } else {
                    float* C = (float*)Cv;
                    *(float2*)(C + (size_t)r0 * N + col) = make_float2(v00, v01);
                    *(float2*)(C + (size_t)(r0 + 8) * N + col) = make_float2(v10, v11);
                }
            }
        }
    } else {
#pragma unroll
        for (int u = 0; u < 2; u++) {
            int col = bn + warp_n * 16 + u * 8 + cpair;
            float b0 = bias[col], b1 = bias[col + 1];
            float m0 = fmaxf(fmaxf(acc[0][u][0], acc[0][u][2]), fmaxf(acc[1][u][0], acc[1][u][2]));
            float m1 = fmaxf(fmaxf(acc[0][u][1], acc[0][u][3]), fmaxf(acc[1][u][1], acc[1][u][3]));
#pragma unroll
            for (int off = 4; off < 32; off <<= 1) {
                m0 = fmaxf(m0, __shfl_xor_sync(0xffffffffu, m0, off));
                m1 = fmaxf(m1, __shfl_xor_sync(0xffffffffu, m1, off));
            }
            m0 = fmaxf(m0 + b0, 0.0f);
            m1 = fmaxf(m1 + b1, 0.0f);
            if (lane < 4) {
                int lc = warp_n * 16 + u * 8 + cpair;
                pool[warp_m][lc] = m0;
                pool[warp_m][lc + 1] = m1;
            }
        }
        __syncthreads();
        if (tid < 64) {
            float v = fmaxf(fmaxf(pool[0][tid], pool[1][tid]),
                            fmaxf(pool[2][tid], pool[3][tid]));
            ((float*)Cv)[(size_t)(bm / POOLG) * N + bn + tid] = v;
        }
    }
}

// ---------------- REDUX argmax helper: max dist (bits), tie -> min index ------
__device__ __forceinline__ void redux_argmax(float bestv, int besti,
                                             unsigned& mxbits, int& widx) {
    unsigned b = __float_as_uint(bestv);
    mxbits = __reduce_max_sync(0xffffffffu, b);
    int cand = (b == mxbits) ? besti : 0x7fffffff;
    widx = __reduce_min_sync(0xffffffffu, cand);
}

// ---------------- FPS level 1: 512 threads, PPT=8, REDUX reduce ----------------
__global__ void fps_kernel(const float* __restrict__ pts, int S,
                           int* __restrict__ outIdx, float* __restrict__ outXyz) {
    const int T = 512;
    const int PPT = 8;
    int b = blockIdx.x;
    int t = threadIdx.x;
    const float* base = pts + (size_t)b * 3 * N1;

    __shared__ float sxp[4096], syp[4096], szp[4096];
    __shared__ float s_c[3];
    __shared__ float s_v[16];
    __shared__ int   s_i[16];

    float px[PPT], py[PPT], pz[PPT], dist[PPT];
#pragma unroll
    for (int j = 0; j < PPT; j++) {
        int i = t + j * T;
        px[j] = base[i];
        py[j] = base[N1 + i];
        pz[j] = base[2 * N1 + i];
        dist[j] = 1e10f;
        sxp[i] = px[j]; syp[i] = py[j]; szp[i] = pz[j];
    }

    if (t == 0) {
        outIdx[(size_t)b * S] = 0;
        float* ox = outXyz + ((size_t)b * S) * 3;
        s_c[0] = sxp[0]; s_c[1] = syp[0]; s_c[2] = szp[0];
        ox[0] = s_c[0]; ox[1] = s_c[1]; ox[2] = s_c[2];
    }
    __syncthreads();

    for (int it = 0; it < S - 1; it++) {
        float cx = s_c[0], cy = s_c[1], cz = s_c[2];
        float bestv; int besti;
        {
            float d = sqd(px[0] - cx, py[0] - cy, pz[0] - cz);
            dist[0] = fminf(dist[0], d);
            bestv = dist[0]; besti = t;
        }
#pragma unroll
        for (int j = 1; j < PPT; j++) {
            float d = sqd(px[j] - cx, py[j] - cy, pz[j] - cz);
            float nd = fminf(dist[j], d);
            dist[j] = nd;
            if (nd > bestv) { bestv = nd; besti = t + j * T; }
        }
        unsigned mx; int wi;
        redux_argmax(bestv, besti, mx, wi);
        if ((t & 31) == 0) { s_v[t >> 5] = __uint_as_float(mx); s_i[t >> 5] = wi; }
        __syncthreads();
        if (t < 32) {
            float v = (t < 16) ? s_v[t] : 0.0f;
            int   ii = (t < 16) ? s_i[t] : 0x7fffffff;
            redux_argmax(v, ii, mx, wi);
            if (t == 0) {
                float nx = sxp[wi], ny = syp[wi], nz = szp[wi];
                s_c[0] = nx; s_c[1] = ny; s_c[2] = nz;
                outIdx[(size_t)b * S + it + 1] = wi;
                float* ox = outXyz + ((size_t)b * S + it + 1) * 3;
                ox[0] = nx; ox[1] = ny; ox[2] = nz;
            }
        }
        __syncthreads();
    }
}

// ---------------- FPS level 2: one WARP per batch ----------------
__global__ void fps_warp(const float* __restrict__ pts, int S,
                         int* __restrict__ outIdx, float* __restrict__ outXyz) {
    const int PPT = 16;
    int b = blockIdx.x;
    int lane = threadIdx.x;
    const float* base = pts + (size_t)b * 512 * 3;

    __shared__ float sx[512], sy[512], sz[512];
    float px[PPT], py[PPT], pz[PPT], dist[PPT];
#pragma unroll
    for (int j = 0; j < PPT; j++) {
        int i = lane + j * 32;
        px[j] = base[i * 3];
        py[j] = base[i * 3 + 1];
        pz[j] = base[i * 3 + 2];
        dist[j] = 1e10f;
        sx[i] = px[j]; sy[i] = py[j]; sz[i] = pz[j];
    }
    __syncwarp();

    float cx = sx[0], cy = sy[0], cz = sz[0];
    if (lane == 0) {
        outIdx[(size_t)b * S] = 0;
        float* ox = outXyz + ((size_t)b * S) * 3;
        ox[0] = cx; ox[1] = cy; ox[2] = cz;
    }

    for (int it = 0; it < S - 1; it++) {
        float bestv; int besti;
        {
            float d = sqd(px[0] - cx, py[0] - cy, pz[0] - cz);
            dist[0] = fminf(dist[0], d);
            bestv = dist[0]; besti = lane;
        }
#pragma unroll
        for (int j = 1; j < PPT; j++) {
            float d = sqd(px[j] - cx, py[j] - cy, pz[j] - cz);
            float nd = fminf(dist[j], d);
            dist[j] = nd;
            if (nd > bestv) { bestv = nd; besti = lane + j * 32; }
        }
        unsigned mx; int wi;
        redux_argmax(bestv, besti, mx, wi);
        cx = sx[wi]; cy = sy[wi]; cz = sz[wi];
        if (lane == 0) {
            outIdx[(size_t)b * S + it + 1] = wi;
            float* ox = outXyz + ((size_t)b * S + it + 1) * 3;
            ox[0] = cx; ox[1] = cy; ox[2] = cz;
        }
    }
}

// ---------------- ball query + grouping, SA1 ----------------
__global__ void bq_group1(const float* __restrict__ xyz,
                          const float* __restrict__ cent,
                          float* __restrict__ out) {
    extern __shared__ float sm[];
    float* sx = sm; float* sy = sm + N1; float* sz = sm + 2 * N1;
    __shared__ int sel[8][G1];
    int b = blockIdx.x;
    const float* base = xyz + (size_t)b * 3 * N1;
    for (int i = threadIdx.x; i < N1; i += blockDim.x) {
        sx[i] = base[i]; sy[i] = base[N1 + i]; sz[i] = base[2 * N1 + i];
    }
    __syncthreads();
    const float R2 = (float)(0.2 * 0.2);
    int warp = threadIdx.x >> 5, lane = threadIdx.x & 31;
    for (int s = blockIdx.y * 8 + warp; s < S1; s += gridDim.y * 8) {
        const float* cc = cent + ((size_t)b * S1 + s) * 3;
        float cx = cc[0], cy = cc[1], cz = cc[2];
        int cnt = 0, first = -1;
        for (int bi = 0; bi < N1; bi += 32) {
            int i = bi + lane;
            float d = sqd(sx[i] - cx, sy[i] - cy, sz[i] - cz);
            bool ok = (d <= R2);
            unsigned m = __ballot_sync(0xffffffffu, ok);
            if (m) {
                if (first < 0) first = bi + __ffs(m) - 1;
                int pos = cnt + __popc(m & ((1u << lane) - 1u));
                if (ok && pos < G1) sel[warp][pos] = i;
                cnt += __popc(m);
                if (cnt >= G1) break;
            }
        }
        for (int p = cnt + lane; p < G1; p += 32) sel[warp][p] = first;
        __syncwarp();
        int i = sel[warp][lane];
        size_t row = (((size_t)(b * S1 + s)) * G1 + lane) * 3;
        out[row + 0] = sx[i] - cx;
        out[row + 1] = sy[i] - cy;
        out[row + 2] = sz[i] - cz;
        __syncwarp();
    }
}

// ---------------- ball query SA2: indices only ----------------
__global__ void bq_group2_idx(const float* __restrict__ pts,
                              const float* __restrict__ cent,
                              int* __restrict__ gidx) {
    __shared__ float sx[512], sy[512], sz[512];
    __shared__ int sel[8][G2];
    int b = blockIdx.x;
    const float* base = pts + (size_t)b * 512 * 3;
    for (int i = threadIdx.x; i < 512; i += blockDim.x) {
        sx[i] = base[i * 3]; sy[i] = base[i * 3 + 1]; sz[i] = base[i * 3 + 2];
    }
    __syncthreads();
    const float R2 = (float)(0.4 * 0.4);
    int warp = threadIdx.x >> 5, lane = threadIdx.x & 31;
    for (int s = blockIdx.y * 8 + warp; s < S2; s += gridDim.y * 8) {
        const float* cc = cent + ((size_t)b * S2 + s) * 3;
        float cx = cc[0], cy = cc[1], cz = cc[2];
        int cnt = 0, first = -1;
        for (int bi = 0; bi < 512; bi += 32) {
            int i = bi + lane;
            float d = sqd(sx[i] - cx, sy[i] - cy, sz[i] - cz);
            bool ok = (d <= R2);
            unsigned m = __ballot_sync(0xffffffffu, ok);
            if (m) {
                if (first < 0) first = bi + __ffs(m) - 1;
                int pos = cnt + __popc(m & ((1u << lane) - 1u));
                if (ok && pos < G2) sel[warp][pos] = i;
                cnt += __popc(m);
                if (cnt >= G2) break;
            }
        }
        for (int p = cnt + lane; p < G2; p += 32) sel[warp][p] = first;
        __syncwarp();
        int* dst = gidx + (size_t)(b * S2 + s) * G2;
        dst[lane] = sel[warp][lane];
        dst[lane + 32] = sel[warp][lane + 32];
        __syncwarp();
    }
}

// ---------------- generic fp32 GEMM (small head layers, M=32) ----------------
#define BM 128
#define BN 64
#define BK 16
__global__ void gemm_bias_act(const float* __restrict__ A, const float* __restrict__ W,
                              const float* __restrict__ bias, float* __restrict__ C,
                              int M, int K, int N, int doRelu) {
    __shared__ float As[BK][BM + 4];
    __shared__ float Ws[BK][BN];
    int bm = blockIdx.x * BM, bn = blockIdx.y * BN;
    int tid = threadIdx.x;
    int tx = tid & 15, ty = tid >> 4;
    float acc[8][4] = {};

    for (int k0 = 0; k0 < K; k0 += BK) {
        int lr = tid >> 1, lk0 = (tid & 1) * 8;
        int gm = bm + lr;
#pragma unroll
        for (int i = 0; i < 8; i++) {
            int kk = k0 + lk0 + i;
            As[lk0 + i][lr] = (gm < M && kk < K) ? A[(size_t)gm * K + kk] : 0.0f;
        }
        int ln = tid >> 2, lkw = (tid & 3) * 4;
        int gn = bn + ln;
#pragma unroll
        for (int i = 0; i < 4; i++) {
            int kk = k0 + lkw + i;
            Ws[lkw + i][ln] = (gn < N && kk < K) ? W[(size_t)gn * K + kk] : 0.0f;
        }
        __syncthreads();
#pragma unroll
        for (int k = 0; k < BK; k++) {
            float a[8], bvv[4];
#pragma unroll
            for (int i = 0; i < 8; i++) a[i] = As[k][ty * 8 + i];
#pragma unroll
            for (int j = 0; j < 4; j++) bvv[j] = Ws[k][tx * 4 + j];
#pragma unroll
            for (int i = 0; i < 8; i++)
#pragma unroll
                for (int j = 0; j < 4; j++) acc[i][j] += a[i] * bvv[j];
        }
        __syncthreads();
    }
#pragma unroll
    for (int j = 0; j < 4; j++) {
        int gn = bn + tx * 4 + j;
        if (gn >= N) continue;
        float bv = bias[gn];
#pragma unroll
        for (int i = 0; i < 8; i++) {
            int gm = bm + ty * 8 + i;
            if (gm < M) {
                float v = acc[i][j] + bv;
                if (doRelu) v = fmaxf(v, 0.0f);
                C[(size_t)gm * N + gn] = v;
            }
        }
    }
}

// ---------------- SA3 concat (PACKED, stride 288) ----------------
__global__ void concat_sa3(const float* __restrict__ cent2, const uint32_t* __restrict__ l2p,
                           uint32_t* __restrict__ out) {
    int idx = blockIdx.x * blockDim.x + threadIdx.x;
    const int TOT = BATCH * S2 * 288;
    if (idx >= TOT) return;
    int r = idx / 288, c = idx - r * 288;
    uint32_t v;
    if (c < 3) v = packv(cent2[r * 3 + c]);
    else if (c < 259) v = l2p[(size_t)r * 256 + (c - 3)];
    else v = 0;
    out[idx] = v;
}

// ---------------- orchestration ----------------
static inline void launch_gemm_simt(const float* A, const float* W, const float* bias, float* C,
                                    int M, int K, int N, int relu) {
    dim3 grid((M + BM - 1) / BM, (N + BN - 1) / BN);
    gemm_bias_act<<<grid, 256>>>(A, W, bias, C, M, K, N, relu);
}

extern "C" void kernel_launch(void* const* d_in, const int* in_sizes, int n_in,
                              void* d_out, int out_size) {
    (void)in_sizes; (void)n_in; (void)out_size;
    const float* xyz  = (const float*)d_in[0];
    const float* s1w0 = (const float*)d_in[1];  const float* s1b0 = (const float*)d_in[2];
    const float* s1w1 = (const float*)d_in[3];  const float* s1b1 = (const float*)d_in[4];
    const float* s1w2 = (const float*)d_in[5];  const float* s1b2 = (const float*)d_in[6];
    const float* s2w0 = (const float*)d_in[7];  const float* s2b0 = (const float*)d_in[8];
    const float* s2w1 = (const float*)d_in[9];  const float* s2b1 = (const float*)d_in[10];
    const float* s2w2 = (const float*)d_in[11]; const float* s2b2 = (const float*)d_in[12];
    const float* s3w0 = (const float*)d_in[13]; const float* s3b0 = (const float*)d_in[14];
    const float* s3w1 = (const float*)d_in[15]; const float* s3b1 = (const float*)d_in[16];
    const float* s3w2 = (const float*)d_in[17]; const float* s3b2 = (const float*)d_in[18];
    const float* f1w  = (const float*)d_in[19]; const float* f1b  = (const float*)d_in[20];
    const float* f2w  = (const float*)d_in[21]; const float* f2b  = (const float*)d_in[22];
    const float* f3w  = (const float*)d_in[23]; const float* f3b  = (const float*)d_in[24];
    float* out = (float*)d_out;

    float *bufA, *bufB, *cent1, *cent2, *l1p, *l2p, *featv;
    int *idx1, *gidx2;
    uint32_t* wpk;
    cudaGetSymbolAddress((void**)&bufA, g_bufA);
    cudaGetSymbolAddress((void**)&bufB, g_bufB);
    cudaGetSymbolAddress((void**)&cent1, g_cent1);
    cudaGetSymbolAddress((void**)&cent2, g_cent2);
    cudaGetSymbolAddress((void**)&l1p, g_l1p);
    cudaGetSymbolAddress((void**)&l2p, g_l2p);
    cudaGetSymbolAddress((void**)&featv, g_feat);
    cudaGetSymbolAddress((void**)&idx1, g_idx1);
    cudaGetSymbolAddress((void**)&gidx2, g_gidx2);
    cudaGetSymbolAddress((void**)&wpk, g_wpk);
    uint32_t* bufA_u = (uint32_t*)bufA;
    uint32_t* bufB_u = (uint32_t*)bufB;
    uint32_t* l1p_u = (uint32_t*)l1p;
    uint32_t* l2p_u = (uint32_t*)l2p;
    float* FP = bufB + FP_OFFSET;   // 16384 x 128 fp32

    cudaFuncSetAttribute(bq_group1, cudaFuncAttributeMaxDynamicSharedMemorySize, 3 * N1 * 4);
    cudaFuncSetAttribute(sa1_fused, cudaFuncAttributeMaxDynamicSharedMemorySize, SA1_SMEM);
    cudaFuncSetAttribute(sa2_fused, cudaFuncAttributeMaxDynamicSharedMemorySize, SA2_SMEM);

    // ---- side streams + fork/join events (created once, outside capture) ----
    static cudaStream_t sB = nullptr, sC = nullptr;
    static cudaEvent_t eRoot, e0, e1, e2;
    if (sB == nullptr) {
        cudaStreamCreateWithFlags(&sB, cudaStreamNonBlocking);
        cudaStreamCreateWithFlags(&sC, cudaStreamNonBlocking);
        cudaEventCreateWithFlags(&eRoot, cudaEventDisableTiming);
        cudaEventCreateWithFlags(&e0, cudaEventDisableTiming);
        cudaEventCreateWithFlags(&e1, cudaEventDisableTiming);
        cudaEventCreateWithFlags(&e2, cudaEventDisableTiming);
    }

    const int M1 = BATCH * S1 * G1;   // 524288

    // fork root from the main (capture) stream
    cudaEventRecord(eRoot, 0);

    // ---- side stream B: weight pre-pack (independent of FPS) ----
    cudaStreamWaitEvent(sB, eRoot, 0);
    {
        PkTab tab;
        auto seg = [&](int i, const float* src, int dst, int N, int Kcopy, int Kp,
                       int srcK, int colOff) {
            tab.s[i].src = src; tab.s[i].dst = dst; tab.s[i].Kp = Kp;
            tab.s[i].srcK = srcK; tab.s[i].colOff = colOff; tab.s[i].Kcopy = Kcopy;
            tab.cum[i + 1] = tab.cum[i] + N * Kp;
        };
        tab.cum[0] = 0;
        seg(0, s1w1, WO_S1W1, 64, 64, 64, 64, 0);
        seg(1, s1w2, WO_S1W2, 128, 64, 64, 64, 0);
        seg(2, s2w1, WO_S2W1, 128, 128, 128, 128, 0);
        seg(3, s2w2, WO_S2W2, 256, 128, 128, 128, 0);
        seg(4, s3w0, WO_S3W0, 256, 259, 288, 259, 0);
        seg(5, s3w1, WO_S3W1, 512, 256, 256, 256, 0);
        seg(6, s3w2, WO_S3W2, 1024, 512, 512, 512, 0);
        seg(7, s2w0, WO_FPW, 128, 128, 128, 131, 3);   // feat cols 3..130
        prepack_all<<<(tab.cum[8] + 255) / 256, 256, 0, sB>>>(tab, wpk);
    }
    cudaEventRecord(e0, sB);

    // ---- main stream: FPS level 1 ----
    fps_kernel<<<BATCH, 512>>>(xyz, S1, idx1, cent1);
    cudaEventRecord(e1, 0);

    // ---- side stream C: SA2 prep (fps_warp + bq2), hidden under SA1 ----
    cudaStreamWaitEvent(sC, e1, 0);
    fps_warp<<<BATCH, 32, 0, sC>>>(cent1, S2, idx1, cent2);
    bq_group2_idx<<<dim3(BATCH, 2), 256, 0, sC>>>(cent1, cent2, gidx2);
    cudaEventRecord(e2, sC);

    // ---- main stream: SA1 chain ----
    bq_group1<<<dim3(BATCH, 8), 256, 3 * N1 * 4>>>(xyz, cent1, bufA);
    cudaStreamWaitEvent(0, e0, 0);   // packed weights ready
    sa1_fused<<<M1 / 128, 512, SA1_SMEM>>>(bufA, s1w0, s1b0,
                                           wpk + WO_S1W1, s1b1, wpk + WO_S1W2, s1b2, l1p_u);

    // ---- feature projection of unique points (dedups SA2 L1) ----
    gemm_str<0, 0, 0><<<dim3(128, 2), 512>>>(l1p_u, wpk + WO_FPW, nullptr, FP,
                                             16384, 128, 128, 128);

    // ---- join side stream C, then SA2 ----
    cudaStreamWaitEvent(0, e2, 0);
    sa2_fused<<<(BATCH * S2 * G2) / 128, 512, SA2_SMEM>>>(
        gidx2, cent1, cent2, FP, s2w0, s2b0,
        wpk + WO_S2W1, s2b1, wpk + WO_S2W2, s2b2, l2p_u);

    // ---- SA3 (group all; M=4096, streaming) ----
    concat_sa3<<<(BATCH * S2 * 288 + 255) / 256, 256>>>(cent2, l2p_u, bufB_u);
    gemm_str<0, 1, 1><<<dim3(32, 4), 512>>>(bufB_u, wpk + WO_S3W0, s3b0, bufA_u, 4096, 288, 288, 256);
    gemm_str<0, 1, 1><<<dim3(32, 8), 512>>>(bufA_u, wpk + WO_S3W1, s3b1, bufB_u, 4096, 256, 256, 512);
    gemm_str<128, 0, 1><<<dim3(32, 16), 512>>>(bufB_u, wpk + WO_S3W2, s3b2, featv, 4096, 512, 512, 1024);

    // ---- head (tiny, fp32) ----
    launch_gemm_simt(featv, f1w, f1b, bufA, BATCH, 1024, 512, 1);
    launch_gemm_simt(bufA, f2w, f2b, bufB, BATCH, 512, 256, 1);
    launch_gemm_simt(bufB, f3w, f3b, out, BATCH, 256, 6, 0);
}

// round 16
// speedup vs baseline: 1.7554x; 1.7554x over previous
#include <cuda_runtime.h>
#include <cuda_bf16.h>
#include <cstdint>

// ---------------- problem constants ----------------
#define BATCH 32
#define N1 4096
#define S1 512
#define G1 32
#define S2 128
#define G2 64

// ---------------- scratch (device globals; no cudaMalloc allowed) ----------------
__device__ float g_bufA[44u * 1024u * 1024u];
__device__ float g_bufB[36u * 1024u * 1024u];
__device__ float g_cent1[BATCH * S1 * 3];
__device__ float g_cent2[BATCH * S2 * 3];
__device__ int   g_idx1[BATCH * S1];
__device__ int   g_gidx2[BATCH * S2 * G2];
__device__ float g_l1p[BATCH * S1 * 128];
__device__ float g_l2p[BATCH * S2 * 256];
__device__ float g_feat[BATCH * 1024];
__device__ uint32_t g_wpk[1024u * 1024u];   // packed split-bf16 weights (4MB)

// packed-weight offsets (words)
#define WO_S1W1 0        // 64 x 64
#define WO_S1W2 4096     // 128 x 64
#define WO_S2W1 32768    // 128 x 128
#define WO_S2W2 49152    // 256 x 128
#define WO_S3W0 81920    // 256 x 288 (K=259)
#define WO_S3W1 155648   // 512 x 256
#define WO_S3W2 286720   // 1024 x 512
#define WO_FPW  811008   // 128 x 128 (cols 3..130 of s2w0)

// FP (unique-point feature projection) buffer: inside g_bufB at float offset 16M
#define FP_OFFSET (16u * 1024u * 1024u)

// squared distance with NO fma contraction, same assoc order as jnp.sum over last axis
__device__ __forceinline__ float sqd(float dx, float dy, float dz) {
    return __fadd_rn(__fadd_rn(__fmul_rn(dx, dx), __fmul_rn(dy, dy)), __fmul_rn(dz, dz));
}

// ================= mma.sync helpers =================
__device__ __forceinline__ uint32_t smem_u32(const void* p) {
    uint32_t a;
    asm("{ .reg .u64 t; cvta.to.shared.u64 t, %1; cvt.u32.u64 %0, t; }" : "=r"(a) : "l"(p));
    return a;
}
__device__ __forceinline__ void ldm_x4(uint32_t addr, uint32_t& r0, uint32_t& r1,
                                       uint32_t& r2, uint32_t& r3) {
    asm volatile("ldmatrix.sync.aligned.m8n8.x4.shared.b16 {%0,%1,%2,%3}, [%4];"
                 : "=r"(r0), "=r"(r1), "=r"(r2), "=r"(r3) : "r"(addr));
}
__device__ __forceinline__ void mma_bf16(float* c, uint32_t a0, uint32_t a1, uint32_t a2,
                                         uint32_t a3, uint32_t b0, uint32_t b1) {
    asm volatile("mma.sync.aligned.m16n8k16.row.col.f32.bf16.bf16.f32 "
                 "{%0,%1,%2,%3}, {%4,%5,%6,%7}, {%8,%9}, {%0,%1,%2,%3};"
                 : "+f"(c[0]), "+f"(c[1]), "+f"(c[2]), "+f"(c[3])
                 : "r"(a0), "r"(a1), "r"(a2), "r"(a3), "r"(b0), "r"(b1));
}
__device__ __forceinline__ uint32_t pack_hi(float v0, float v1, float& rl0, float& rl1) {
    __nv_bfloat16 h0 = __float2bfloat16(v0);
    __nv_bfloat16 h1 = __float2bfloat16(v1);
    rl0 = v0 - __bfloat162float(h0);
    rl1 = v1 - __bfloat162float(h1);
    return ((uint32_t)__bfloat16_as_ushort(h1) << 16) | (uint32_t)__bfloat16_as_ushort(h0);
}
__device__ __forceinline__ uint32_t pack_lo(float l0, float l1) {
    return ((uint32_t)__bfloat16_as_ushort(__float2bfloat16(l1)) << 16) |
           (uint32_t)__bfloat16_as_ushort(__float2bfloat16(l0));
}
__device__ __forceinline__ uint32_t packv(float v) {
    __nv_bfloat16 h = __float2bfloat16(v);
    float l = v - __bfloat162float(h);
    return ((uint32_t)__bfloat16_as_ushort(__float2bfloat16(l)) << 16) |
           (uint32_t)__bfloat16_as_ushort(h);
}

// ---------------- merged weight pre-pack (one launch) ----------------
struct PkSeg { const float* src; int dst; int Kp; int srcK; int colOff; int Kcopy; };
struct PkTab { PkSeg s[8]; int cum[9]; };

__global__ void prepack_all(PkTab tab, uint32_t* __restrict__ out) {
    int idx = blockIdx.x * blockDim.x + threadIdx.x;
    if (idx >= tab.cum[8]) return;
    int si = 0;
    while (idx >= tab.cum[si + 1]) si++;
    int loc = idx - tab.cum[si];
    PkSeg sg = tab.s[si];
    int r = loc / sg.Kp, c = loc - r * sg.Kp;
    float v = (c < sg.Kcopy) ? sg.src[(size_t)r * sg.srcK + sg.colOff + c] : 0.0f;
    out[sg.dst + loc] = packv(v);
}

// ======================================================================
// One MMA layer over a 128-row smem-resident input tile.
// 512 threads, 4x4 warps, warp tile 32x16.  out = relu(in @ W^T + bias).
// ======================================================================
template <int POOLG, int OUT_SMEM, int OUT_PACKED>
__device__ __forceinline__ void mma_layer(
    const __nv_bfloat16* sInH, const __nv_bfloat16* sInL, int ldaeIn, int Kp,
    const uint32_t* __restrict__ Wp, int Kw, const float* __restrict__ bias, int N,
    __nv_bfloat16* sOutH, __nv_bfloat16* sOutL, int ldaeOut,
    void* Cv, int bm,
    __nv_bfloat16 (*sWh)[40], __nv_bfloat16 (*sWl)[40], float* pool) {
    const int tid = threadIdx.x;
    const int lane = tid & 31;
    const int wid = tid >> 5;
    const int warp_m = wid & 3;
    const int warp_n = wid >> 2;

    const uint32_t aInH = smem_u32(sInH);
    const uint32_t aInL = smem_u32(sInL);
    const uint32_t aWh = smem_u32(&sWh[0][0]);
    const uint32_t aWl = smem_u32(&sWl[0][0]);
    const int a_r = warp_m * 32 + (lane & 15);
    const int a_c = (lane >> 4) << 3;
    const int b_r = warp_n * 16 + ((lane >> 4) << 3) + (lane & 7);
    const int b_c = ((lane >> 3) & 1) << 3;
    const uint32_t baseAh = aInH + (uint32_t)(a_r * ldaeIn + a_c) * 2;
    const uint32_t baseAl = aInL + (uint32_t)(a_r * ldaeIn + a_c) * 2;
    const uint32_t stepT = (uint32_t)(16 * ldaeIn * 2);
    const uint32_t baseWh = aWh + (uint32_t)(b_r * 40 + b_c) * 2;
    const uint32_t baseWl = aWl + (uint32_t)(b_r * 40 + b_c) * 2;

    const int nch = Kp >> 5;
    const int g = lane >> 2;
    const int cpair = (lane & 3) << 1;

    for (int nb = 0; nb < (N >> 6); nb++) {
        const int bn = nb << 6;
        float acc[2][2][4];
#pragma unroll
        for (int t = 0; t < 2; t++)
#pragma unroll
            for (int u = 0; u < 2; u++)
#pragma unroll
                for (int i = 0; i < 4; i++) acc[t][u][i] = 0.0f;

        for (int kc = 0; kc < nch; kc++) {
            const int k0 = kc << 5;
            // ---- fill W tiles from packed: 64 rows x 32 words, 1 uint4/thread ----
            {
                int r = tid >> 3, q = tid & 7;
                uint4 v = *(const uint4*)(Wp + (size_t)(bn + r) * Kw + k0 + q * 4);
                uint32_t h01 = __byte_perm(v.x, v.y, 0x5410);
                uint32_t l01 = __byte_perm(v.x, v.y, 0x7632);
                uint32_t h23 = __byte_perm(v.z, v.w, 0x5410);
                uint32_t l23 = __byte_perm(v.z, v.w, 0x7632);
                *(uint2*)&sWh[r][q * 4] = make_uint2(h01, h23);
                *(uint2*)&sWl[r][q * 4] = make_uint2(l01, l23);
            }
            __syncthreads();

#pragma unroll
            for (int ks = 0; ks < 2; ks++) {
                const uint32_t koffA = (uint32_t)((k0 + (ks << 4)) * 2);
                const uint32_t koffW = (uint32_t)((ks << 4) * 2);
                uint32_t ah[2][4], al[2][4];
#pragma unroll
                for (int t = 0; t < 2; t++) {
                    ldm_x4(baseAh + t * stepT + koffA, ah[t][0], ah[t][1], ah[t][2], ah[t][3]);
                    ldm_x4(baseAl + t * stepT + koffA, al[t][0], al[t][1], al[t][2], al[t][3]);
                }
                uint32_t bh[4], bl[4];
                ldm_x4(baseWh + koffW, bh[0], bh[1], bh[2], bh[3]);
                ldm_x4(baseWl + koffW, bl[0], bl[1], bl[2], bl[3]);
#pragma unroll
                for (int t = 0; t < 2; t++)
#pragma unroll
                    for (int u = 0; u < 2; u++) {
                        mma_bf16(acc[t][u], ah[t][0], ah[t][1], ah[t][2], ah[t][3], bh[2 * u], bh[2 * u + 1]);
                        mma_bf16(acc[t][u], ah[t][0], ah[t][1], ah[t][2], ah[t][3], bl[2 * u], bl[2 * u + 1]);
                        mma_bf16(acc[t][u], al[t][0], al[t][1], al[t][2], al[t][3], bh[2 * u], bh[2 * u + 1]);
                    }
            }
            __syncthreads();
        }

        if (POOLG == 0) {
#pragma unroll
            for (int t = 0; t < 2; t++) {
#pragma unroll
                for (int u = 0; u < 2; u++) {
                    int col = bn + warp_n * 16 + u * 8 + cpair;
                    float b0 = bias[col], b1 = bias[col + 1];
                    float v00 = fmaxf(acc[t][u][0] + b0, 0.0f);
                    float v01 = fmaxf(acc[t][u][1] + b1, 0.0f);
                    float v10 = fmaxf(acc[t][u][2] + b0, 0.0f);
                    float v11 = fmaxf(acc[t][u][3] + b1, 0.0f);
                    if (OUT_SMEM) {
                        int r0 = warp_m * 32 + t * 16 + g;
                        float l0, l1;
                        uint32_t h0w = pack_hi(v00, v01, l0, l1);
                        uint32_t l0w = pack_lo(l0, l1);
                        *(uint32_t*)((uint16_t*)sOutH + (size_t)r0 * ldaeOut + col) = h0w;
                        *(uint32_t*)((uint16_t*)sOutL + (size_t)r0 * ldaeOut + col) = l0w;
                        uint32_t h1w = pack_hi(v10, v11, l0, l1);
                        uint32_t l1w = pack_lo(l0, l1);
                        *(uint32_t*)((uint16_t*)sOutH + (size_t)(r0 + 8) * ldaeOut + col) = h1w;
                        *(uint32_t*)((uint16_t*)sOutL + (size_t)(r0 + 8) * ldaeOut + col) = l1w;
                    } else {
                        int r0 = bm + warp_m * 32 + t * 16 + g;
                        if (OUT_PACKED) {
                            uint32_t* C = (uint32_t*)Cv;
                            *(uint2*)(C + (size_t)r0 * N + col) = make_uint2(packv(v00), packv(v01));
                            *(uint2*)(C + (size_t)(r0 + 8) * N + col) = make_uint2(packv(v10), packv(v11));
                        } else {
                            float* C = (float*)Cv;
                            *(float2*)(C + (size_t)r0 * N + col) = make_float2(v00, v01);
                            *(float2*)(C + (size_t)(r0 + 8) * N + col) = make_float2(v10, v11);
                        }
                    }
                }
            }
        } else {
#pragma unroll
            for (int u = 0; u < 2; u++) {
                int col = bn + warp_n * 16 + u * 8 + cpair;
                float b0 = bias[col], b1 = bias[col + 1];
                float m0 = fmaxf(fmaxf(acc[0][u][0], acc[0][u][2]), fmaxf(acc[1][u][0], acc[1][u][2]));
                float m1 = fmaxf(fmaxf(acc[0][u][1], acc[0][u][3]), fmaxf(acc[1][u][1], acc[1][u][3]));
#pragma unroll
                for (int off = 4; off < 32; off <<= 1) {
                    m0 = fmaxf(m0, __shfl_xor_sync(0xffffffffu, m0, off));
                    m1 = fmaxf(m1, __shfl_xor_sync(0xffffffffu, m1, off));
                }
                m0 = fmaxf(m0 + b0, 0.0f);
                m1 = fmaxf(m1 + b1, 0.0f);
                if (POOLG == 32) {
                    if (lane < 4) {
                        int s = bm / 32 + warp_m;
                        uint32_t* C = (uint32_t*)Cv;
                        *(uint2*)(C + (size_t)s * N + col) = make_uint2(packv(m0), packv(m1));
                    }
                } else {
                    if (lane < 4) {
                        int lc = warp_n * 16 + u * 8 + cpair;
                        pool[warp_m * 64 + lc] = m0;
                        pool[warp_m * 64 + lc + 1] = m1;
                    }
                }
            }
            if (POOLG == 64) {
                __syncthreads();
                if (tid < 128) {
                    int gg = tid >> 6, c = tid & 63;
                    float v = fmaxf(pool[2 * gg * 64 + c], pool[(2 * gg + 1) * 64 + c]);
                    ((uint32_t*)Cv)[(size_t)(bm / 64 + gg) * N + bn + c] = packv(v);
                }
                __syncthreads();
            }
        }
    }
    __syncthreads();
}

// ======================================================================
// SA1 fused: L0 gen (3->64) -> L1 (64->64) -> L2 (64->128) + pool32
// ======================================================================
#define SA1_SMEM 88064
__global__ __launch_bounds__(512, 2)
void sa1_fused(const float* __restrict__ GXYZ,
               const float* __restrict__ W0, const float* __restrict__ B0,
               const uint32_t* __restrict__ W1p, const float* __restrict__ b1,
               const uint32_t* __restrict__ W2p, const float* __restrict__ b2,
               uint32_t* __restrict__ l1p) {
    extern __shared__ char smem[];
    __nv_bfloat16* t0H = (__nv_bfloat16*)(smem);
    __nv_bfloat16* t0L = (__nv_bfloat16*)(smem + 18432);
    __nv_bfloat16* t1H = (__nv_bfloat16*)(smem + 36864);
    __nv_bfloat16* t1L = (__nv_bfloat16*)(smem + 55296);
    __nv_bfloat16 (*sWh)[40] = (__nv_bfloat16(*)[40])(smem + 73728);
    __nv_bfloat16 (*sWl)[40] = (__nv_bfloat16(*)[40])(smem + 78848);
    float* pool = (float*)(smem + 83968);
    float* sxyz = (float*)(smem + 84992);
    float* sW0 = sxyz + 512;
    float* sB0 = sW0 + 192;

    const int tid = threadIdx.x;
    const int bm = blockIdx.x * 128;
    const int ldae = 72;

    if (tid < 192) sW0[tid] = W0[tid];
    if (tid >= 192 && tid < 256) sB0[tid - 192] = B0[tid - 192];
    if (tid >= 256 && tid < 384) {
        int r = tid - 256;
        const float* g = GXYZ + (size_t)(bm + r) * 3;
        sxyz[r * 4] = g[0]; sxyz[r * 4 + 1] = g[1]; sxyz[r * 4 + 2] = g[2];
    }
    __syncthreads();
#pragma unroll
    for (int i = 0; i < 8; i++) {
        int idx = (i << 9) + tid;
        int r = idx >> 5;
        int pc = (idx & 31) << 1;
        float x = sxyz[r * 4], y = sxyz[r * 4 + 1], z = sxyz[r * 4 + 2];
        float v0 = fmaxf(sB0[pc] + x * sW0[pc * 3] + y * sW0[pc * 3 + 1] + z * sW0[pc * 3 + 2], 0.0f);
        float v1 = fmaxf(sB0[pc + 1] + x * sW0[pc * 3 + 3] + y * sW0[pc * 3 + 4] + z * sW0[pc * 3 + 5], 0.0f);
        float l0, l1;
        uint32_t ph = pack_hi(v0, v1, l0, l1);
        *(uint32_t*)&t0H[r * ldae + pc] = ph;
        *(uint32_t*)&t0L[r * ldae + pc] = pack_lo(l0, l1);
    }
    __syncthreads();

    mma_layer<0, 1, 0>(t0H, t0L, 72, 64, W1p, 64, b1, 64,
                       t1H, t1L, 72, nullptr, bm, sWh, sWl, pool);
    mma_layer<32, 0, 1>(t1H, t1L, 72, 64, W2p, 64, b2, 128,
                        nullptr, nullptr, 0, l1p, bm, sWh, sWl, pool);
}

// ======================================================================
// SA2 fused (deduped L1): fill t1 = relu(FP[i] + b1 + W1xyz . xyz_rel)
//   -> L2 (128->128) -> L3 (128->256)+pool64
// ======================================================================
#define SA2_SMEM 152576
__global__ __launch_bounds__(512)
void sa2_fused(const int* __restrict__ gidx,
               const float* __restrict__ cent1, const float* __restrict__ cent2,
               const float* __restrict__ FP,
               const float* __restrict__ W0src, const float* __restrict__ b1,
               const uint32_t* __restrict__ W2p, const float* __restrict__ b2,
               const uint32_t* __restrict__ W3p, const float* __restrict__ b3,
               uint32_t* __restrict__ l2p) {
    extern __shared__ char smem[];
    __nv_bfloat16* t1H = (__nv_bfloat16*)(smem);
    __nv_bfloat16* t1L = (__nv_bfloat16*)(smem + 34816);
    __nv_bfloat16* t2H = (__nv_bfloat16*)(smem + 69632);
    __nv_bfloat16* t2L = (__nv_bfloat16*)(smem + 104448);
    __nv_bfloat16 (*sWh)[40] = (__nv_bfloat16(*)[40])(smem + 139264);
    __nv_bfloat16 (*sWl)[40] = (__nv_bfloat16(*)[40])(smem + 144384);
    float* pool = (float*)(smem + 149504);
    float* wx = (float*)(smem + 150528);
    float* wy = (float*)(smem + 151040);
    float* wz = (float*)(smem + 151552);
    float* sb1 = (float*)(smem + 152064);

    const int tid = threadIdx.x;
    const int bm = blockIdx.x * 128;

    if (tid < 128) {
        wx[tid] = W0src[tid * 131];
        wy[tid] = W0src[tid * 131 + 1];
        wz[tid] = W0src[tid * 131 + 2];
        sb1[tid] = b1[tid];
    }
    __syncthreads();

    // ---- fill t1 directly: relu(FPfeat + bias + xyz part), pack hi/lo ----
    {
        const int r = tid >> 2, q = tid & 3;
        const int gr = bm + r;
        const int bs = gr >> 6;
        const int n = gr & 63;
        const int b = bs >> 7;
        const int i = gidx[(size_t)bs * 64 + n];
        const float* p1 = cent1 + ((size_t)b * 512 + i) * 3;
        const float* p2 = cent2 + (size_t)bs * 3;
        float dx = p1[0] - p2[0], dy = p1[1] - p2[1], dz = p1[2] - p2[2];
        const float* fprow = FP + ((size_t)b * 512 + i) * 128;
        uint16_t* dh = (uint16_t*)t1H + (size_t)r * 136;
        uint16_t* dl = (uint16_t*)t1L + (size_t)r * 136;
        const int c0 = q * 32;
#pragma unroll
        for (int c = c0; c < c0 + 32; c += 2) {
            float v0 = fmaxf(fprow[c] + sb1[c] + wx[c] * dx + wy[c] * dy + wz[c] * dz, 0.0f);
            float v1 = fmaxf(fprow[c + 1] + sb1[c + 1] + wx[c + 1] * dx + wy[c + 1] * dy + wz[c + 1] * dz, 0.0f);
            float l0, l1;
            uint32_t hw = pack_hi(v0, v1, l0, l1);
            *(uint32_t*)(dh + c) = hw;
            *(uint32_t*)(dl + c) = pack_lo(l0, l1);
        }
    }
    __syncthreads();

    mma_layer<0, 1, 0>(t1H, t1L, 136, 128, W2p, 128, b2, 128,
                       t2H, t2L, 136, nullptr, bm, sWh, sWl, pool);
    mma_layer<64, 0, 1>(t2H, t2L, 136, 128, W3p, 128, b3, 256,
                        nullptr, nullptr, 0, l2p, bm, sWh, sWl, pool);
}

// ======================================================================
// STREAMING GEMM, 512 threads, packed A and packed W.
// DOBR: 1 = add bias + relu; 0 = raw accumulation output (fp32 only).
// ======================================================================
#define LDA 40
template <int POOLG, int OUT_PACKED, int DOBR>
__global__ __launch_bounds__(512, 2)
void gemm_str(const uint32_t* __restrict__ A, const uint32_t* __restrict__ Wp,
              const float* __restrict__ bias, void* __restrict__ Cv,
              int M, int Kw, int Kp, int N) {
    __shared__ __nv_bfloat16 sAh[128][LDA];
    __shared__ __nv_bfloat16 sAl[128][LDA];
    __shared__ __nv_bfloat16 sWh[64][LDA];
    __shared__ __nv_bfloat16 sWl[64][LDA];
    __shared__ float pool[4][64];

    const int tid = threadIdx.x;
    const int lane = tid & 31;
    const int wid = tid >> 5;
    const int warp_m = wid & 3;
    const int warp_n = wid >> 2;
    const int bm = blockIdx.x * 128, bn = blockIdx.y * 64;

    float acc[2][2][4];
#pragma unroll
    for (int t = 0; t < 2; t++)
#pragma unroll
        for (int u = 0; u < 2; u++)
#pragma unroll
            for (int i = 0; i < 4; i++) acc[t][u][i] = 0.0f;

    const uint32_t aAh = smem_u32(&sAh[0][0]);
    const uint32_t aAl = smem_u32(&sAl[0][0]);
    const uint32_t aWh = smem_u32(&sWh[0][0]);
    const uint32_t aWl = smem_u32(&sWl[0][0]);
    const int a_r = warp_m * 32 + (lane & 15);
    const int a_c = (lane >> 4) << 3;
    const int b_r = warp_n * 16 + ((lane >> 4) << 3) + (lane & 7);
    const int b_c = ((lane >> 3) & 1) << 3;
    const uint32_t baseAh = aAh + (uint32_t)(a_r * LDA + a_c) * 2;
    const uint32_t baseAl = aAl + (uint32_t)(a_r * LDA + a_c) * 2;
    const uint32_t baseWh = aWh + (uint32_t)(b_r * LDA + b_c) * 2;
    const uint32_t baseWl = aWl + (uint32_t)(b_r * LDA + b_c) * 2;
    const uint32_t stepT = (uint32_t)(16 * LDA * 2);

    const int nch = Kp >> 5;
    for (int kc = 0; kc < nch; kc++) {
        const int k0 = kc << 5;
        __syncthreads();
        {
            const int r = tid >> 2, q = tid & 3;
            const uint4* arow = (const uint4*)(A + (size_t)(bm + r) * Kp + k0 + q * 8);
            char* dh = (char*)&sAh[r][q * 8];
            char* dl = (char*)&sAl[r][q * 8];
#pragma unroll
            for (int j = 0; j < 2; j++) {
                uint4 v = arow[j];
                uint32_t h01 = __byte_perm(v.x, v.y, 0x5410);
                uint32_t l01 = __byte_perm(v.x, v.y, 0x7632);
                uint32_t h23 = __byte_perm(v.z, v.w, 0x5410);
                uint32_t l23 = __byte_perm(v.z, v.w, 0x7632);
                *(uint2*)(dh + j * 8) = make_uint2(h01, h23);
                *(uint2*)(dl + j * 8) = make_uint2(l01, l23);
            }
        }
        {
            int r = tid >> 3, q = tid & 7;
            uint4 v = *(const uint4*)(Wp + (size_t)(bn + r) * Kw + k0 + q * 4);
            uint32_t h01 = __byte_perm(v.x, v.y, 0x5410);
            uint32_t l01 = __byte_perm(v.x, v.y, 0x7632);
            uint32_t h23 = __byte_perm(v.z, v.w, 0x5410);
            uint32_t l23 = __byte_perm(v.z, v.w, 0x7632);
            *(uint2*)&sWh[r][q * 4] = make_uint2(h01, h23);
            *(uint2*)&sWl[r][q * 4] = make_uint2(l01, l23);
        }
        __syncthreads();

#pragma unroll
        for (int ks = 0; ks < 2; ks++) {
            const uint32_t koff = (uint32_t)((ks << 4) * 2);
            uint32_t ah[2][4], al[2][4];
#pragma unroll
            for (int t = 0; t < 2; t++) {
                ldm_x4(baseAh + t * stepT + koff, ah[t][0], ah[t][1], ah[t][2], ah[t][3]);
                ldm_x4(baseAl + t * stepT + koff, al[t][0], al[t][1], al[t][2], al[t][3]);
            }
            uint32_t bh[4], bl[4];
            ldm_x4(baseWh + koff, bh[0], bh[1], bh[2], bh[3]);
            ldm_x4(baseWl + koff, bl[0], bl[1], bl[2], bl[3]);
#pragma unroll
            for (int t = 0; t < 2; t++)
#pragma unroll
                for (int u = 0; u < 2; u++) {
                    mma_bf16(acc[t][u], ah[t][0], ah[t][1], ah[t][2], ah[t][3], bh[2 * u], bh[2 * u + 1]);
                    mma_bf16(acc[t][u], ah[t][0], ah[t][1], ah[t][2], ah[t][3], bl[2 * u], bl[2 * u + 1]);
                    mma_bf16(acc[t][u], al[t][0], al[t][1], al[t][2], al[t][3], bh[2 * u], bh[2 * u + 1]);
                }
        }
    }

    const int g = lane >> 2;
    const int cpair = (lane & 3) << 1;
    if (POOLG == 0) {
#pragma unroll
        for (int t = 0; t < 2; t++) {
#pragma unroll
            for (int u = 0; u < 2; u++) {
                int col = bn + warp_n * 16 + u * 8 + cpair;
                float v00 = acc[t][u][0], v01 = acc[t][u][1];
                float v10 = acc[t][u][2], v11 = acc[t][u][3];
                if (DOBR) {
                    float b0 = bias[col], b1 = bias[col + 1];
                    v00 = fmaxf(v00 + b0, 0.0f); v01 = fmaxf(v01 + b1, 0.0f);
                    v10 = fmaxf(v10 + b0, 0.0f); v11 = fmaxf(v11 + b1, 0.0f);
                }
                int r0 = bm + warp_m * 32 + t * 16 + g;
                if (OUT_PACKED) {
                    uint32_t* C = (uint32_t*)Cv;
                    *(uint2*)(C + (size_t)r0 * N + col) = make_uint2(packv(v00), packv(v01));
                    *(uint2*)(C + (size_t)(r0 + 8) * N + col) = make_uint2(packv(v10), packv(v11));
                } else {
                    float* C = (float*)Cv;
                    *(float2*)(C + (size_t)r0 * N + col) = make_float2(v00, v01);
                    *(float2*)(C + (size_t)(r0 + 8) * N + col) = make_float2(v10, v11);
                }
            }
        }
    } else {
#pragma unroll
        for (int u = 0; u < 2; u++) {
            int col = bn + warp_n * 16 + u * 8 + cpair;
            float b0 = bias[col], b1 = bias[col + 1];
            float m0 = fmaxf(fmaxf(acc[0][u][0], acc[0][u][2]), fmaxf(acc[1][u][0], acc[1][u][2]));
            float m1 = fmaxf(fmaxf(acc[0][u][1], acc[0][u][3]), fmaxf(acc[1][u][1], acc[1][u][3]));
#pragma unroll
            for (int off = 4; off < 32; off <<= 1) {
                m0 = fmaxf(m0, __shfl_xor_sync(0xffffffffu, m0, off));
                m1 = fmaxf(m1, __shfl_xor_sync(0xffffffffu, m1, off));
            }
            m0 = fmaxf(m0 + b0, 0.0f);
            m1 = fmaxf(m1 + b1, 0.0f);
            if (lane < 4) {
                int lc = warp_n * 16 + u * 8 + cpair;
                pool[warp_m][lc] = m0;
                pool[warp_m][lc + 1] = m1;
            }
        }
        __syncthreads();
        if (tid < 64) {
            float v = fmaxf(fmaxf(pool[0][tid], pool[1][tid]),
                            fmaxf(pool[2][tid], pool[3][tid]));
            ((float*)Cv)[(size_t)(bm / POOLG) * N + bn + tid] = v;
        }
    }
}

// ---------------- REDUX argmax helper: max dist (bits), tie -> min index ------
__device__ __forceinline__ void redux_argmax(float bestv, int besti,
                                             unsigned& mxbits, int& widx) {
    unsigned b = __float_as_uint(bestv);
    mxbits = __reduce_max_sync(0xffffffffu, b);
    int cand = (b == mxbits) ? besti : 0x7fffffff;
    widx = __reduce_min_sync(0xffffffffu, cand);
}

// ---------------- FPS level 1: 512 threads, PPT=8, REDUX reduce ----------------
__global__ void fps_kernel(const float* __restrict__ pts, int S,
                           int* __restrict__ outIdx, float* __restrict__ outXyz) {
    const int T = 512;
    const int PPT = 8;
    int b = blockIdx.x;
    int t = threadIdx.x;
    const float* base = pts + (size_t)b * 3 * N1;

    __shared__ float sxp[4096], syp[4096], szp[4096];
    __shared__ float s_c[3];
    __shared__ float s_v[16];
    __shared__ int   s_i[16];

    float px[PPT], py[PPT], pz[PPT], dist[PPT];
#pragma unroll
    for (int j = 0; j < PPT; j++) {
        int i = t + j * T;
        px[j] = base[i];
        py[j] = base[N1 + i];
        pz[j] = base[2 * N1 + i];
        dist[j] = 1e10f;
        sxp[i] = px[j]; syp[i] = py[j]; szp[i] = pz[j];
    }

    if (t == 0) {
        outIdx[(size_t)b * S] = 0;
        float* ox = outXyz + ((size_t)b * S) * 3;
        s_c[0] = sxp[0]; s_c[1] = syp[0]; s_c[2] = szp[0];
        ox[0] = s_c[0]; ox[1] = s_c[1]; ox[2] = s_c[2];
    }
    __syncthreads();

    for (int it = 0; it < S - 1; it++) {
        float cx = s_c[0], cy = s_c[1], cz = s_c[2];
        float bestv; int besti;
        {
            float d = sqd(px[0] - cx, py[0] - cy, pz[0] - cz);
            dist[0] = fminf(dist[0], d);
            bestv = dist[0]; besti = t;
        }
#pragma unroll
        for (int j = 1; j < PPT; j++) {
            float d = sqd(px[j] - cx, py[j] - cy, pz[j] - cz);
            float nd = fminf(dist[j], d);
            dist[j] = nd;
            if (nd > bestv) { bestv = nd; besti = t + j * T; }
        }
        unsigned mx; int wi;
        redux_argmax(bestv, besti, mx, wi);
        if ((t & 31) == 0) { s_v[t >> 5] = __uint_as_float(mx); s_i[t >> 5] = wi; }
        __syncthreads();
        if (t < 32) {
            float v = (t < 16) ? s_v[t] : 0.0f;
            int   ii = (t < 16) ? s_i[t] : 0x7fffffff;
            redux_argmax(v, ii, mx, wi);
            if (t == 0) {
                float nx = sxp[wi], ny = syp[wi], nz = szp[wi];
                s_c[0] = nx; s_c[1] = ny; s_c[2] = nz;
                outIdx[(size_t)b * S + it + 1] = wi;
                float* ox = outXyz + ((size_t)b * S + it + 1) * 3;
                ox[0] = nx; ox[1] = ny; ox[2] = nz;
            }
        }
        __syncthreads();
    }
}

// ---------------- FPS level 2: one WARP per batch ----------------
__global__ void fps_warp(const float* __restrict__ pts, int S,
                         int* __restrict__ outIdx, float* __restrict__ outXyz) {
    const int PPT = 16;
    int b = blockIdx.x;
    int lane = threadIdx.x;
    const float* base = pts + (size_t)b * 512 * 3;

    __shared__ float sx[512], sy[512], sz[512];
    float px[PPT], py[PPT], pz[PPT], dist[PPT];
#pragma unroll
    for (int j = 0; j < PPT; j++) {
        int i = lane + j * 32;
        px[j] = base[i * 3];
        py[j] = base[i * 3 + 1];
        pz[j] = base[i * 3 + 2];
        dist[j] = 1e10f;
        sx[i] = px[j]; sy[i] = py[j]; sz[i] = pz[j];
    }
    __syncwarp();

    float cx = sx[0], cy = sy[0], cz = sz[0];
    if (lane == 0) {
        outIdx[(size_t)b * S] = 0;
        float* ox = outXyz + ((size_t)b * S) * 3;
        ox[0] = cx; ox[1] = cy; ox[2] = cz;
    }

    for (int it = 0; it < S - 1; it++) {
        float bestv; int besti;
        {
            float d = sqd(px[0] - cx, py[0] - cy, pz[0] - cz);
            dist[0] = fminf(dist[0], d);
            bestv = dist[0]; besti = lane;
        }
#pragma unroll
        for (int j = 1; j < PPT; j++) {
            float d = sqd(px[j] - cx, py[j] - cy, pz[j] - cz);
            float nd = fminf(dist[j], d);
            dist[j] = nd;
            if (nd > bestv) { bestv = nd; besti = lane + j * 32; }
        }
        unsigned mx; int wi;
        redux_argmax(bestv, besti, mx, wi);
        cx = sx[wi]; cy = sy[wi]; cz = sz[wi];
        if (lane == 0) {
            outIdx[(size_t)b * S + it + 1] = wi;
            float* ox = outXyz + ((size_t)b * S + it + 1) * 3;
            ox[0] = cx; ox[1] = cy; ox[2] = cz;
        }
    }
}

// ---------------- ball query + grouping, SA1 ----------------
__global__ void bq_group1(const float* __restrict__ xyz,
                          const float* __restrict__ cent,
                          float* __restrict__ out) {
    extern __shared__ float sm[];
    float* sx = sm; float* sy = sm + N1; float* sz = sm + 2 * N1;
    __shared__ int sel[8][G1];
    int b = blockIdx.x;
    const float* base = xyz + (size_t)b * 3 * N1;
    for (int i = threadIdx.x; i < N1; i += blockDim.x) {
        sx[i] = base[i]; sy[i] = base[N1 + i]; sz[i] = base[2 * N1 + i];
    }
    __syncthreads();
    const float R2 = (float)(0.2 * 0.2);
    int warp = threadIdx.x >> 5, lane = threadIdx.x & 31;
    for (int s = blockIdx.y * 8 + warp; s < S1; s += gridDim.y * 8) {
        const float* cc = cent + ((size_t)b * S1 + s) * 3;
        float cx = cc[0], cy = cc[1], cz = cc[2];
        int cnt = 0, first = -1;
        for (int bi = 0; bi < N1; bi += 32) {
            int i = bi + lane;
            float d = sqd(sx[i] - cx, sy[i] - cy, sz[i] - cz);
            bool ok = (d <= R2);
            unsigned m = __ballot_sync(0xffffffffu, ok);
            if (m) {
                if (first < 0) first = bi + __ffs(m) - 1;
                int pos = cnt + __popc(m & ((1u << lane) - 1u));
                if (ok && pos < G1) sel[warp][pos] = i;
                cnt += __popc(m);
                if (cnt >= G1) break;
            }
        }
        for (int p = cnt + lane; p < G1; p += 32) sel[warp][p] = first;
        __syncwarp();
        int i = sel[warp][lane];
        size_t row = (((size_t)(b * S1 + s)) * G1 + lane) * 3;
        out[row + 0] = sx[i] - cx;
        out[row + 1] = sy[i] - cy;
        out[row + 2] = sz[i] - cz;
        __syncwarp();
    }
}

// ---------------- ball query SA2: indices only ----------------
__global__ void bq_group2_idx(const float* __restrict__ pts,
                              const float* __restrict__ cent,
                              int* __restrict__ gidx) {
    __shared__ float sx[512], sy[512], sz[512];
    __shared__ int sel[8][G2];
    int b = blockIdx.x;
    const float* base = pts + (size_t)b * 512 * 3;
    for (int i = threadIdx.x; i < 512; i += blockDim.x) {
        sx[i] = base[i * 3]; sy[i] = base[i * 3 + 1]; sz[i] = base[i * 3 + 2];
    }
    __syncthreads();
    const float R2 = (float)(0.4 * 0.4);
    int warp = threadIdx.x >> 5, lane = threadIdx.x & 31;
    for (int s = blockIdx.y * 8 + warp; s < S2; s += gridDim.y * 8) {
        const float* cc = cent + ((size_t)b * S2 + s) * 3;
        float cx = cc[0], cy = cc[1], cz = cc[2];
        int cnt = 0, first = -1;
        for (int bi = 0; bi < 512; bi += 32) {
            int i = bi + lane;
            float d = sqd(sx[i] - cx, sy[i] - cy, sz[i] - cz);
            bool ok = (d <= R2);
            unsigned m = __ballot_sync(0xffffffffu, ok);
            if (m) {
                if (first < 0) first = bi + __ffs(m) - 1;
                int pos = cnt + __popc(m & ((1u << lane) - 1u));
                if (ok && pos < G2) sel[warp][pos] = i;
                cnt += __popc(m);
                if (cnt >= G2) break;
            }
        }
        for (int p = cnt + lane; p < G2; p += 32) sel[warp][p] = first;
        __syncwarp();
        int* dst = gidx + (size_t)(b * S2 + s) * G2;
        dst[lane] = sel[warp][lane];
        dst[lane + 32] = sel[warp][lane + 32];
        __syncwarp();
    }
}

// ---------------- generic fp32 GEMM (small head layers, M=32) ----------------
#define BM 128
#define BN 64
#define BK 16
__global__ void gemm_bias_act(const float* __restrict__ A, const float* __restrict__ W,
                              const float* __restrict__ bias, float* __restrict__ C,
                              int M, int K, int N, int doRelu) {
    __shared__ float As[BK][BM + 4];
    __shared__ float Ws[BK][BN];
    int bm = blockIdx.x * BM, bn = blockIdx.y * BN;
    int tid = threadIdx.x;
    int tx = tid & 15, ty = tid >> 4;
    float acc[8][4] = {};

    for (int k0 = 0; k0 < K; k0 += BK) {
        int lr = tid >> 1, lk0 = (tid & 1) * 8;
        int gm = bm + lr;
#pragma unroll
        for (int i = 0; i < 8; i++) {
            int kk = k0 + lk0 + i;
            As[lk0 + i][lr] = (gm < M && kk < K) ? A[(size_t)gm * K + kk] : 0.0f;
        }
        int ln = tid >> 2, lkw = (tid & 3) * 4;
        int gn = bn + ln;
#pragma unroll
        for (int i = 0; i < 4; i++) {
            int kk = k0 + lkw + i;
            Ws[lkw + i][ln] = (gn < N && kk < K) ? W[(size_t)gn * K + kk] : 0.0f;
        }
        __syncthreads();
#pragma unroll
        for (int k = 0; k < BK; k++) {
            float a[8], bvv[4];
#pragma unroll
            for (int i = 0; i < 8; i++) a[i] = As[k][ty * 8 + i];
#pragma unroll
            for (int j = 0; j < 4; j++) bvv[j] = Ws[k][tx * 4 + j];
#pragma unroll
            for (int i = 0; i < 8; i++)
#pragma unroll
                for (int j = 0; j < 4; j++) acc[i][j] += a[i] * bvv[j];
        }
        __syncthreads();
    }
#pragma unroll
    for (int j = 0; j < 4; j++) {
        int gn = bn + tx * 4 + j;
        if (gn >= N) continue;
        float bv = bias[gn];
#pragma unroll
        for (int i = 0; i < 8; i++) {
            int gm = bm + ty * 8 + i;
            if (gm < M) {
                float v = acc[i][j] + bv;
                if (doRelu) v = fmaxf(v, 0.0f);
                C[(size_t)gm * N + gn] = v;
            }
        }
    }
}

// ---------------- SA3 concat (PACKED, stride 288) ----------------
__global__ void concat_sa3(const float* __restrict__ cent2, const uint32_t* __restrict__ l2p,
                           uint32_t* __restrict__ out) {
    int idx = blockIdx.x * blockDim.x + threadIdx.x;
    const int TOT = BATCH * S2 * 288;
    if (idx >= TOT) return;
    int r = idx / 288, c = idx - r * 288;
    uint32_t v;
    if (c < 3) v = packv(cent2[r * 3 + c]);
    else if (c < 259) v = l2p[(size_t)r * 256 + (c - 3)];
    else v = 0;
    out[idx] = v;
}

// ---------------- orchestration ----------------
static inline void launch_gemm_simt(const float* A, const float* W, const float* bias, float* C,
                                    int M, int K, int N, int relu) {
    dim3 grid((M + BM - 1) / BM, (N + BN - 1) / BN);
    gemm_bias_act<<<grid, 256>>>(A, W, bias, C, M, K, N, relu);
}

extern "C" void kernel_launch(void* const* d_in, const int* in_sizes, int n_in,
                              void* d_out, int out_size) {
    (void)in_sizes; (void)n_in; (void)out_size;
    const float* xyz  = (const float*)d_in[0];
    const float* s1w0 = (const float*)d_in[1];  const float* s1b0 = (const float*)d_in[2];
    const float* s1w1 = (const float*)d_in[3];  const float* s1b1 = (const float*)d_in[4];
    const float* s1w2 = (const float*)d_in[5];  const float* s1b2 = (const float*)d_in[6];
    const float* s2w0 = (const float*)d_in[7];  const float* s2b0 = (const float*)d_in[8];
    const float* s2w1 = (const float*)d_in[9];  const float* s2b1 = (const float*)d_in[10];
    const float* s2w2 = (const float*)d_in[11]; const float* s2b2 = (const float*)d_in[12];
    const float* s3w0 = (const float*)d_in[13]; const float* s3b0 = (const float*)d_in[14];
    const float* s3w1 = (const float*)d_in[15]; const float* s3b1 = (const float*)d_in[16];
    const float* s3w2 = (const float*)d_in[17]; const float* s3b2 = (const float*)d_in[18];
    const float* f1w  = (const float*)d_in[19]; const float* f1b  = (const float*)d_in[20];
    const float* f2w  = (const float*)d_in[21]; const float* f2b  = (const float*)d_in[22];
    const float* f3w  = (const float*)d_in[23]; const float* f3b  = (const float*)d_in[24];
    float* out = (float*)d_out;

    float *bufA, *bufB, *cent1, *cent2, *l1p, *l2p, *featv;
    int *idx1, *gidx2;
    uint32_t* wpk;
    cudaGetSymbolAddress((void**)&bufA, g_bufA);
    cudaGetSymbolAddress((void**)&bufB, g_bufB);
    cudaGetSymbolAddress((void**)&cent1, g_cent1);
    cudaGetSymbolAddress((void**)&cent2, g_cent2);
    cudaGetSymbolAddress((void**)&l1p, g_l1p);
    cudaGetSymbolAddress((void**)&l2p, g_l2p);
    cudaGetSymbolAddress((void**)&featv, g_feat);
    cudaGetSymbolAddress((void**)&idx1, g_idx1);
    cudaGetSymbolAddress((void**)&gidx2, g_gidx2);
    cudaGetSymbolAddress((void**)&wpk, g_wpk);
    uint32_t* bufA_u = (uint32_t*)bufA;
    uint32_t* bufB_u = (uint32_t*)bufB;
    uint32_t* l1p_u = (uint32_t*)l1p;
    uint32_t* l2p_u = (uint32_t*)l2p;
    float* FP = bufB + FP_OFFSET;   // 16384 x 128 fp32

    cudaFuncSetAttribute(bq_group1, cudaFuncAttributeMaxDynamicSharedMemorySize, 3 * N1 * 4);
    cudaFuncSetAttribute(sa1_fused, cudaFuncAttributeMaxDynamicSharedMemorySize, SA1_SMEM);
    cudaFuncSetAttribute(sa2_fused, cudaFuncAttributeMaxDynamicSharedMemorySize, SA2_SMEM);

    const int M1 = BATCH * S1 * G1;   // 524288

    // ---- single merged weight pre-pack ----
    {
        PkTab tab;
        auto seg = [&](int i, const float* src, int dst, int N, int Kcopy, int Kp,
                       int srcK, int colOff) {
            tab.s[i].src = src; tab.s[i].dst = dst; tab.s[i].Kp = Kp;
            tab.s[i].srcK = srcK; tab.s[i].colOff = colOff; tab.s[i].Kcopy = Kcopy;
            tab.cum[i + 1] = tab.cum[i] + N * Kp;
        };
        tab.cum[0] = 0;
        seg(0, s1w1, WO_S1W1, 64, 64, 64, 64, 0);
        seg(1, s1w2, WO_S1W2, 128, 64, 64, 64, 0);
        seg(2, s2w1, WO_S2W1, 128, 128, 128, 128, 0);
        seg(3, s2w2, WO_S2W2, 256, 128, 128, 128, 0);
        seg(4, s3w0, WO_S3W0, 256, 259, 288, 259, 0);
        seg(5, s3w1, WO_S3W1, 512, 256, 256, 256, 0);
        seg(6, s3w2, WO_S3W2, 1024, 512, 512, 512, 0);
        seg(7, s2w0, WO_FPW, 128, 128, 128, 131, 3);   // feat cols 3..130
        prepack_all<<<(tab.cum[8] + 255) / 256, 256>>>(tab, wpk);
    }

    // ---- SA1 ----
    fps_kernel<<<BATCH, 512>>>(xyz, S1, idx1, cent1);
    bq_group1<<<dim3(BATCH, 8), 256, 3 * N1 * 4>>>(xyz, cent1, bufA);
    sa1_fused<<<M1 / 128, 512, SA1_SMEM>>>(bufA, s1w0, s1b0,
                                           wpk + WO_S1W1, s1b1, wpk + WO_S1W2, s1b2, l1p_u);

    // ---- feature projection of unique points (dedups SA2 L1) ----
    gemm_str<0, 0, 0><<<dim3(128, 2), 512>>>(l1p_u, wpk + WO_FPW, nullptr, FP,
                                             16384, 128, 128, 128);

    // ---- SA2 ----
    fps_warp<<<BATCH, 32>>>(cent1, S2, idx1, cent2);
    bq_group2_idx<<<dim3(BATCH, 2), 256>>>(cent1, cent2, gidx2);
    sa2_fused<<<(BATCH * S2 * G2) / 128, 512, SA2_SMEM>>>(
        gidx2, cent1, cent2, FP, s2w0, s2b0,
        wpk + WO_S2W1, s2b1, wpk + WO_S2W2, s2b2, l2p_u);

    // ---- SA3 (group all; M=4096, streaming) ----
    concat_sa3<<<(BATCH * S2 * 288 + 255) / 256, 256>>>(cent2, l2p_u, bufB_u);
    gemm_str<0, 1, 1><<<dim3(32, 4), 512>>>(bufB_u, wpk + WO_S3W0, s3b0, bufA_u, 4096, 288, 288, 256);
    gemm_str<0, 1, 1><<<dim3(32, 8), 512>>>(bufA_u, wpk + WO_S3W1, s3b1, bufB_u, 4096, 256, 256, 512);
    gemm_str<128, 0, 1><<<dim3(32, 16), 512>>>(bufB_u, wpk + WO_S3W2, s3b2, featv, 4096, 512, 512, 1024);

    // ---- head (tiny, fp32) ----
    launch_gemm_simt(featv, f1w, f1b, bufA, BATCH, 1024, 512, 1);
    launch_gemm_simt(bufA, f2w, f2b, bufB, BATCH, 512, 256, 1);
    launch_gemm_simt(bufB, f3w, f3b, out, BATCH, 256, 6, 0);
}

// round 17
// speedup vs baseline: 1.7580x; 1.0015x over previous
#include <cuda_runtime.h>
#include <cuda_bf16.h>
#include <cstdint>

// ---------------- problem constants ----------------
#define BATCH 32
#define N1 4096
#define S1 512
#define G1 32
#define S2 128
#define G2 64

// ---------------- scratch (device globals; no cudaMalloc allowed) ----------------
__device__ float g_bufA[44u * 1024u * 1024u];
__device__ float g_bufB[36u * 1024u * 1024u];
__device__ float g_cent1[BATCH * S1 * 3];
__device__ float g_cent2[BATCH * S2 * 3];
__device__ int   g_idx1[BATCH * S1];
__device__ int   g_gidx2[BATCH * S2 * G2];
__device__ float g_l1p[BATCH * S1 * 128];
__device__ float g_l2p[BATCH * S2 * 256];
__device__ float g_feat[BATCH * 1024];
__device__ uint32_t g_wpk[1024u * 1024u];   // packed split-bf16 weights (4MB)

// packed-weight offsets (words)
#define WO_S1W1 0        // 64 x 64
#define WO_S1W2 4096     // 128 x 64
#define WO_S2W1 32768    // 128 x 128
#define WO_S2W2 49152    // 256 x 128
#define WO_S3W0 81920    // 256 x 288 (K=259)
#define WO_S3W1 155648   // 512 x 256
#define WO_S3W2 286720   // 1024 x 512
#define WO_FPW  811008   // 128 x 128 (cols 3..130 of s2w0)

// FP (unique-point feature projection) buffer: inside g_bufB at float offset 16M
#define FP_OFFSET (16u * 1024u * 1024u)

// squared distance with NO fma contraction, same assoc order as jnp.sum over last axis
__device__ __forceinline__ float sqd(float dx, float dy, float dz) {
    return __fadd_rn(__fadd_rn(__fmul_rn(dx, dx), __fmul_rn(dy, dy)), __fmul_rn(dz, dz));
}

// ================= mma.sync helpers =================
__device__ __forceinline__ uint32_t smem_u32(const void* p) {
    uint32_t a;
    asm("{ .reg .u64 t; cvta.to.shared.u64 t, %1; cvt.u32.u64 %0, t; }" : "=r"(a) : "l"(p));
    return a;
}
__device__ __forceinline__ void ldm_x4(uint32_t addr, uint32_t& r0, uint32_t& r1,
                                       uint32_t& r2, uint32_t& r3) {
    asm volatile("ldmatrix.sync.aligned.m8n8.x4.shared.b16 {%0,%1,%2,%3}, [%4];"
                 : "=r"(r0), "=r"(r1), "=r"(r2), "=r"(r3) : "r"(addr));
}
__device__ __forceinline__ void mma_bf16(float* c, uint32_t a0, uint32_t a1, uint32_t a2,
                                         uint32_t a3, uint32_t b0, uint32_t b1) {
    asm volatile("mma.sync.aligned.m16n8k16.row.col.f32.bf16.bf16.f32 "
                 "{%0,%1,%2,%3}, {%4,%5,%6,%7}, {%8,%9}, {%0,%1,%2,%3};"
                 : "+f"(c[0]), "+f"(c[1]), "+f"(c[2]), "+f"(c[3])
                 : "r"(a0), "r"(a1), "r"(a2), "r"(a3), "r"(b0), "r"(b1));
}
__device__ __forceinline__ uint32_t pack_hi(float v0, float v1, float& rl0, float& rl1) {
    __nv_bfloat16 h0 = __float2bfloat16(v0);
    __nv_bfloat16 h1 = __float2bfloat16(v1);
    rl0 = v0 - __bfloat162float(h0);
    rl1 = v1 - __bfloat162float(h1);
    return ((uint32_t)__bfloat16_as_ushort(h1) << 16) | (uint32_t)__bfloat16_as_ushort(h0);
}
__device__ __forceinline__ uint32_t pack_lo(float l0, float l1) {
    return ((uint32_t)__bfloat16_as_ushort(__float2bfloat16(l1)) << 16) |
           (uint32_t)__bfloat16_as_ushort(__float2bfloat16(l0));
}
__device__ __forceinline__ uint32_t packv(float v) {
    __nv_bfloat16 h = __float2bfloat16(v);
    float l = v - __bfloat162float(h);
    return ((uint32_t)__bfloat16_as_ushort(__float2bfloat16(l)) << 16) |
           (uint32_t)__bfloat16_as_ushort(h);
}

// ---------------- merged weight pre-pack (one launch) ----------------
struct PkSeg { const float* src; int dst; int Kp; int srcK; int colOff; int Kcopy; };
struct PkTab { PkSeg s[8]; int cum[9]; };

__global__ void prepack_all(PkTab tab, uint32_t* __restrict__ out) {
    int idx = blockIdx.x * blockDim.x + threadIdx.x;
    if (idx >= tab.cum[8]) return;
    int si = 0;
    while (idx >= tab.cum[si + 1]) si++;
    int loc = idx - tab.cum[si];
    PkSeg sg = tab.s[si];
    int r = loc / sg.Kp, c = loc - r * sg.Kp;
    float v = (c < sg.Kcopy) ? sg.src[(size_t)r * sg.srcK + sg.colOff + c] : 0.0f;
    out[sg.dst + loc] = packv(v);
}

// ======================================================================
// One MMA layer over a 128-row smem-resident input tile.
// 512 threads, 4x4 warps, warp tile 32x16.  out = relu(in @ W^T + bias).
// ======================================================================
template <int POOLG, int OUT_SMEM, int OUT_PACKED>
__device__ __forceinline__ void mma_layer(
    const __nv_bfloat16* sInH, const __nv_bfloat16* sInL, int ldaeIn, int Kp,
    const uint32_t* __restrict__ Wp, int Kw, const float* __restrict__ bias, int N,
    __nv_bfloat16* sOutH, __nv_bfloat16* sOutL, int ldaeOut,
    void* Cv, int bm,
    __nv_bfloat16 (*sWh)[40], __nv_bfloat16 (*sWl)[40], float* pool) {
    const int tid = threadIdx.x;
    const int lane = tid & 31;
    const int wid = tid >> 5;
    const int warp_m = wid & 3;
    const int warp_n = wid >> 2;

    const uint32_t aInH = smem_u32(sInH);
    const uint32_t aInL = smem_u32(sInL);
    const uint32_t aWh = smem_u32(&sWh[0][0]);
    const uint32_t aWl = smem_u32(&sWl[0][0]);
    const int a_r = warp_m * 32 + (lane & 15);
    const int a_c = (lane >> 4) << 3;
    const int b_r = warp_n * 16 + ((lane >> 4) << 3) + (lane & 7);
    const int b_c = ((lane >> 3) & 1) << 3;
    const uint32_t baseAh = aInH + (uint32_t)(a_r * ldaeIn + a_c) * 2;
    const uint32_t baseAl = aInL + (uint32_t)(a_r * ldaeIn + a_c) * 2;
    const uint32_t stepT = (uint32_t)(16 * ldaeIn * 2);
    const uint32_t baseWh = aWh + (uint32_t)(b_r * 40 + b_c) * 2;
    const uint32_t baseWl = aWl + (uint32_t)(b_r * 40 + b_c) * 2;

    const int nch = Kp >> 5;
    const int g = lane >> 2;
    const int cpair = (lane & 3) << 1;

    for (int nb = 0; nb < (N >> 6); nb++) {
        const int bn = nb << 6;
        float acc[2][2][4];
#pragma unroll
        for (int t = 0; t < 2; t++)
#pragma unroll
            for (int u = 0; u < 2; u++)
#pragma unroll
                for (int i = 0; i < 4; i++) acc[t][u][i] = 0.0f;

        for (int kc = 0; kc < nch; kc++) {
            const int k0 = kc << 5;
            // ---- fill W tiles from packed: 64 rows x 32 words, 1 uint4/thread ----
            {
                int r = tid >> 3, q = tid & 7;
                uint4 v = *(const uint4*)(Wp + (size_t)(bn + r) * Kw + k0 + q * 4);
                uint32_t h01 = __byte_perm(v.x, v.y, 0x5410);
                uint32_t l01 = __byte_perm(v.x, v.y, 0x7632);
                uint32_t h23 = __byte_perm(v.z, v.w, 0x5410);
                uint32_t l23 = __byte_perm(v.z, v.w, 0x7632);
                *(uint2*)&sWh[r][q * 4] = make_uint2(h01, h23);
                *(uint2*)&sWl[r][q * 4] = make_uint2(l01, l23);
            }
            __syncthreads();

#pragma unroll
            for (int ks = 0; ks < 2; ks++) {
                const uint32_t koffA = (uint32_t)((k0 + (ks << 4)) * 2);
                const uint32_t koffW = (uint32_t)((ks << 4) * 2);
                uint32_t ah[2][4], al[2][4];
#pragma unroll
                for (int t = 0; t < 2; t++) {
                    ldm_x4(baseAh + t * stepT + koffA, ah[t][0], ah[t][1], ah[t][2], ah[t][3]);
                    ldm_x4(baseAl + t * stepT + koffA, al[t][0], al[t][1], al[t][2], al[t][3]);
                }
                uint32_t bh[4], bl[4];
                ldm_x4(baseWh + koffW, bh[0], bh[1], bh[2], bh[3]);
                ldm_x4(baseWl + koffW, bl[0], bl[1], bl[2], bl[3]);
#pragma unroll
                for (int t = 0; t < 2; t++)
#pragma unroll
                    for (int u = 0; u < 2; u++) {
                        mma_bf16(acc[t][u], ah[t][0], ah[t][1], ah[t][2], ah[t][3], bh[2 * u], bh[2 * u + 1]);
                        mma_bf16(acc[t][u], ah[t][0], ah[t][1], ah[t][2], ah[t][3], bl[2 * u], bl[2 * u + 1]);
                        mma_bf16(acc[t][u], al[t][0], al[t][1], al[t][2], al[t][3], bh[2 * u], bh[2 * u + 1]);
                    }
            }
            __syncthreads();
        }

        if (POOLG == 0) {
#pragma unroll
            for (int t = 0; t < 2; t++) {
#pragma unroll
                for (int u = 0; u < 2; u++) {
                    int col = bn + warp_n * 16 + u * 8 + cpair;
                    float b0 = bias[col], b1 = bias[col + 1];
                    float v00 = fmaxf(acc[t][u][0] + b0, 0.0f);
                    float v01 = fmaxf(acc[t][u][1] + b1, 0.0f);
                    float v10 = fmaxf(acc[t][u][2] + b0, 0.0f);
                    float v11 = fmaxf(acc[t][u][3] + b1, 0.0f);
                    if (OUT_SMEM) {
                        int r0 = warp_m * 32 + t * 16 + g;
                        float l0, l1;
                        uint32_t h0w = pack_hi(v00, v01, l0, l1);
                        uint32_t l0w = pack_lo(l0, l1);
                        *(uint32_t*)((uint16_t*)sOutH + (size_t)r0 * ldaeOut + col) = h0w;
                        *(uint32_t*)((uint16_t*)sOutL + (size_t)r0 * ldaeOut + col) = l0w;
                        uint32_t h1w = pack_hi(v10, v11, l0, l1);
                        uint32_t l1w = pack_lo(l0, l1);
                        *(uint32_t*)((uint16_t*)sOutH + (size_t)(r0 + 8) * ldaeOut + col) = h1w;
                        *(uint32_t*)((uint16_t*)sOutL + (size_t)(r0 + 8) * ldaeOut + col) = l1w;
                    } else {
                        int r0 = bm + warp_m * 32 + t * 16 + g;
                        if (OUT_PACKED) {
                            uint32_t* C = (uint32_t*)Cv;
                            *(uint2*)(C + (size_t)r0 * N + col) = make_uint2(packv(v00), packv(v01));
                            *(uint2*)(C + (size_t)(r0 + 8) * N + col) = make_uint2(packv(v10), packv(v11));
                        } else {
                            float* C = (float*)Cv;
                            *(float2*)(C + (size_t)r0 * N + col) = make_float2(v00, v01);
                            *(float2*)(C + (size_t)(r0 + 8) * N + col) = make_float2(v10, v11);
                        }
                    }
                }
            }
        } else {
#pragma unroll
            for (int u = 0; u < 2; u++) {
                int col = bn + warp_n * 16 + u * 8 + cpair;
                float b0 = bias[col], b1 = bias[col + 1];
                float m0 = fmaxf(fmaxf(acc[0][u][0], acc[0][u][2]), fmaxf(acc[1][u][0], acc[1][u][2]));
                float m1 = fmaxf(fmaxf(acc[0][u][1], acc[0][u][3]), fmaxf(acc[1][u][1], acc[1][u][3]));
#pragma unroll
                for (int off = 4; off < 32; off <<= 1) {
                    m0 = fmaxf(m0, __shfl_xor_sync(0xffffffffu, m0, off));
                    m1 = fmaxf(m1, __shfl_xor_sync(0xffffffffu, m1, off));
                }
                m0 = fmaxf(m0 + b0, 0.0f);
                m1 = fmaxf(m1 + b1, 0.0f);
                if (POOLG == 32) {
                    if (lane < 4) {
                        int s = bm / 32 + warp_m;
                        uint32_t* C = (uint32_t*)Cv;
                        *(uint2*)(C + (size_t)s * N + col) = make_uint2(packv(m0), packv(m1));
                    }
                } else {
                    if (lane < 4) {
                        int lc = warp_n * 16 + u * 8 + cpair;
                        pool[warp_m * 64 + lc] = m0;
                        pool[warp_m * 64 + lc + 1] = m1;
                    }
                }
            }
            if (POOLG == 64) {
                __syncthreads();
                if (tid < 128) {
                    int gg = tid >> 6, c = tid & 63;
                    float v = fmaxf(pool[2 * gg * 64 + c], pool[(2 * gg + 1) * 64 + c]);
                    ((uint32_t*)Cv)[(size_t)(bm / 64 + gg) * N + bn + c] = packv(v);
                }
                __syncthreads();
            }
        }
    }
    __syncthreads();
}

// ======================================================================
// SA1 fused: L0 gen (3->64) -> L1 (64->64) -> L2 (64->128) + pool32
// ======================================================================
#define SA1_SMEM 88064
__global__ __launch_bounds__(512, 2)
void sa1_fused(const float* __restrict__ GXYZ,
               const float* __restrict__ W0, const float* __restrict__ B0,
               const uint32_t* __restrict__ W1p, const float* __restrict__ b1,
               const uint32_t* __restrict__ W2p, const float* __restrict__ b2,
               uint32_t* __restrict__ l1p) {
    extern __shared__ char smem[];
    __nv_bfloat16* t0H = (__nv_bfloat16*)(smem);
    __nv_bfloat16* t0L = (__nv_bfloat16*)(smem + 18432);
    __nv_bfloat16* t1H = (__nv_bfloat16*)(smem + 36864);
    __nv_bfloat16* t1L = (__nv_bfloat16*)(smem + 55296);
    __nv_bfloat16 (*sWh)[40] = (__nv_bfloat16(*)[40])(smem + 73728);
    __nv_bfloat16 (*sWl)[40] = (__nv_bfloat16(*)[40])(smem + 78848);
    float* pool = (float*)(smem + 83968);
    float* sxyz = (float*)(smem + 84992);
    float* sW0 = sxyz + 512;
    float* sB0 = sW0 + 192;

    const int tid = threadIdx.x;
    const int bm = blockIdx.x * 128;
    const int ldae = 72;

    if (tid < 192) sW0[tid] = W0[tid];
    if (tid >= 192 && tid < 256) sB0[tid - 192] = B0[tid - 192];
    if (tid >= 256 && tid < 384) {
        int r = tid - 256;
        const float* g = GXYZ + (size_t)(bm + r) * 3;
        sxyz[r * 4] = g[0]; sxyz[r * 4 + 1] = g[1]; sxyz[r * 4 + 2] = g[2];
    }
    __syncthreads();
#pragma unroll
    for (int i = 0; i < 8; i++) {
        int idx = (i << 9) + tid;
        int r = idx >> 5;
        int pc = (idx & 31) << 1;
        float x = sxyz[r * 4], y = sxyz[r * 4 + 1], z = sxyz[r * 4 + 2];
        float v0 = fmaxf(sB0[pc] + x * sW0[pc * 3] + y * sW0[pc * 3 + 1] + z * sW0[pc * 3 + 2], 0.0f);
        float v1 = fmaxf(sB0[pc + 1] + x * sW0[pc * 3 + 3] + y * sW0[pc * 3 + 4] + z * sW0[pc * 3 + 5], 0.0f);
        float l0, l1;
        uint32_t ph = pack_hi(v0, v1, l0, l1);
        *(uint32_t*)&t0H[r * ldae + pc] = ph;
        *(uint32_t*)&t0L[r * ldae + pc] = pack_lo(l0, l1);
    }
    __syncthreads();

    mma_layer<0, 1, 0>(t0H, t0L, 72, 64, W1p, 64, b1, 64,
                       t1H, t1L, 72, nullptr, bm, sWh, sWl, pool);
    mma_layer<32, 0, 1>(t1H, t1L, 72, 64, W2p, 64, b2, 128,
                        nullptr, nullptr, 0, l1p, bm, sWh, sWl, pool);
}

// ======================================================================
// SA2 fused (deduped L1): fill t1 = relu(FP[i] + b1 + W1xyz . xyz_rel)
//   -> L2 (128->128) -> L3 (128->256)+pool64
// ======================================================================
#define SA2_SMEM 152576
__global__ __launch_bounds__(512)
void sa2_fused(const int* __restrict__ gidx,
               const float* __restrict__ cent1, const float* __restrict__ cent2,
               const float* __restrict__ FP,
               const float* __restrict__ W0src, const float* __restrict__ b1,
               const uint32_t* __restrict__ W2p, const float* __restrict__ b2,
               const uint32_t* __restrict__ W3p, const float* __restrict__ b3,
               uint32_t* __restrict__ l2p) {
    extern __shared__ char smem[];
    __nv_bfloat16* t1H = (__nv_bfloat16*)(smem);
    __nv_bfloat16* t1L = (__nv_bfloat16*)(smem + 34816);
    __nv_bfloat16* t2H = (__nv_bfloat16*)(smem + 69632);
    __nv_bfloat16* t2L = (__nv_bfloat16*)(smem + 104448);
    __nv_bfloat16 (*sWh)[40] = (__nv_bfloat16(*)[40])(smem + 139264);
    __nv_bfloat16 (*sWl)[40] = (__nv_bfloat16(*)[40])(smem + 144384);
    float* pool = (float*)(smem + 149504);
    float* wx = (float*)(smem + 150528);
    float* wy = (float*)(smem + 151040);
    float* wz = (float*)(smem + 151552);
    float* sb1 = (float*)(smem + 152064);

    const int tid = threadIdx.x;
    const int bm = blockIdx.x * 128;

    if (tid < 128) {
        wx[tid] = W0src[tid * 131];
        wy[tid] = W0src[tid * 131 + 1];
        wz[tid] = W0src[tid * 131 + 2];
        sb1[tid] = b1[tid];
    }
    __syncthreads();

    // ---- fill t1 directly: relu(FPfeat + bias + xyz part), pack hi/lo ----
    {
        const int r = tid >> 2, q = tid & 3;
        const int gr = bm + r;
        const int bs = gr >> 6;
        const int n = gr & 63;
        const int b = bs >> 7;
        const int i = gidx[(size_t)bs * 64 + n];
        const float* p1 = cent1 + ((size_t)b * 512 + i) * 3;
        const float* p2 = cent2 + (size_t)bs * 3;
        float dx = p1[0] - p2[0], dy = p1[1] - p2[1], dz = p1[2] - p2[2];
        const float* fprow = FP + ((size_t)b * 512 + i) * 128;
        uint16_t* dh = (uint16_t*)t1H + (size_t)r * 136;
        uint16_t* dl = (uint16_t*)t1L + (size_t)r * 136;
        const int c0 = q * 32;
#pragma unroll
        for (int c = c0; c < c0 + 32; c += 2) {
            float v0 = fmaxf(fprow[c] + sb1[c] + wx[c] * dx + wy[c] * dy + wz[c] * dz, 0.0f);
            float v1 = fmaxf(fprow[c + 1] + sb1[c + 1] + wx[c + 1] * dx + wy[c + 1] * dy + wz[c + 1] * dz, 0.0f);
            float l0, l1;
            uint32_t hw = pack_hi(v0, v1, l0, l1);
            *(uint32_t*)(dh + c) = hw;
            *(uint32_t*)(dl + c) = pack_lo(l0, l1);
        }
    }
    __syncthreads();

    mma_layer<0, 1, 0>(t1H, t1L, 136, 128, W2p, 128, b2, 128,
                       t2H, t2L, 136, nullptr, bm, sWh, sWl, pool);
    mma_layer<64, 0, 1>(t2H, t2L, 136, 128, W3p, 128, b3, 256,
                        nullptr, nullptr, 0, l2p, bm, sWh, sWl, pool);
}

// ======================================================================
// STREAMING GEMM, 512 threads, packed A and packed W.
// DOBR: 1 = add bias + relu; 0 = raw accumulation output (fp32 only).
// ======================================================================
#define LDA 40
template <int POOLG, int OUT_PACKED, int DOBR>
__global__ __launch_bounds__(512, 2)
void gemm_str(const uint32_t* __restrict__ A, const uint32_t* __restrict__ Wp,
              const float* __restrict__ bias, void* __restrict__ Cv,
              int M, int Kw, int Kp, int N) {
    __shared__ __nv_bfloat16 sAh[128][LDA];
    __shared__ __nv_bfloat16 sAl[128][LDA];
    __shared__ __nv_bfloat16 sWh[64][LDA];
    __shared__ __nv_bfloat16 sWl[64][LDA];
    __shared__ float pool[4][64];

    const int tid = threadIdx.x;
    const int lane = tid & 31;
    const int wid = tid >> 5;
    const int warp_m = wid & 3;
    const int warp_n = wid >> 2;
    const int bm = blockIdx.x * 128, bn = blockIdx.y * 64;

    float acc[2][2][4];
#pragma unroll
    for (int t = 0; t < 2; t++)
#pragma unroll
        for (int u = 0; u < 2; u++)
#pragma unroll
            for (int i = 0; i < 4; i++) acc[t][u][i] = 0.0f;

    const uint32_t aAh = smem_u32(&sAh[0][0]);
    const uint32_t aAl = smem_u32(&sAl[0][0]);
    const uint32_t aWh = smem_u32(&sWh[0][0]);
    const uint32_t aWl = smem_u32(&sWl[0][0]);
    const int a_r = warp_m * 32 + (lane & 15);
    const int a_c = (lane >> 4) << 3;
    const int b_r = warp_n * 16 + ((lane >> 4) << 3) + (lane & 7);
    const int b_c = ((lane >> 3) & 1) << 3;
    const uint32_t baseAh = aAh + (uint32_t)(a_r * LDA + a_c) * 2;
    const uint32_t baseAl = aAl + (uint32_t)(a_r * LDA + a_c) * 2;
    const uint32_t baseWh = aWh + (uint32_t)(b_r * LDA + b_c) * 2;
    const uint32_t baseWl = aWl + (uint32_t)(b_r * LDA + b_c) * 2;
    const uint32_t stepT = (uint32_t)(16 * LDA * 2);

    const int nch = Kp >> 5;
    for (int kc = 0; kc < nch; kc++) {
        const int k0 = kc << 5;
        __syncthreads();
        {
            const int r = tid >> 2, q = tid & 3;
            const uint4* arow = (const uint4*)(A + (size_t)(bm + r) * Kp + k0 + q * 8);
            char* dh = (char*)&sAh[r][q * 8];
            char* dl = (char*)&sAl[r][q * 8];
#pragma unroll
            for (int j = 0; j < 2; j++) {
                uint4 v = arow[j];
                uint32_t h01 = __byte_perm(v.x, v.y, 0x5410);
                uint32_t l01 = __byte_perm(v.x, v.y, 0x7632);
                uint32_t h23 = __byte_perm(v.z, v.w, 0x5410);
                uint32_t l23 = __byte_perm(v.z, v.w, 0x7632);
                *(uint2*)(dh + j * 8) = make_uint2(h01, h23);
                *(uint2*)(dl + j * 8) = make_uint2(l01, l23);
            }
        }
        {
            int r = tid >> 3, q = tid & 7;
            uint4 v = *(const uint4*)(Wp + (size_t)(bn + r) * Kw + k0 + q * 4);
            uint32_t h01 = __byte_perm(v.x, v.y, 0x5410);
            uint32_t l01 = __byte_perm(v.x, v.y, 0x7632);
            uint32_t h23 = __byte_perm(v.z, v.w, 0x5410);
            uint32_t l23 = __byte_perm(v.z, v.w, 0x7632);
            *(uint2*)&sWh[r][q * 4] = make_uint2(h01, h23);
            *(uint2*)&sWl[r][q * 4] = make_uint2(l01, l23);
        }
        __syncthreads();

#pragma unroll
        for (int ks = 0; ks < 2; ks++) {
            const uint32_t koff = (uint32_t)((ks << 4) * 2);
            uint32_t ah[2][4], al[2][4];
#pragma unroll
            for (int t = 0; t < 2; t++) {
                ldm_x4(baseAh + t * stepT + koff, ah[t][0], ah[t][1], ah[t][2], ah[t][3]);
                ldm_x4(baseAl + t * stepT + koff, al[t][0], al[t][1], al[t][2], al[t][3]);
            }
            uint32_t bh[4], bl[4];
            ldm_x4(baseWh + koff, bh[0], bh[1], bh[2], bh[3]);
            ldm_x4(baseWl + koff, bl[0], bl[1], bl[2], bl[3]);
#pragma unroll
            for (int t = 0; t < 2; t++)
#pragma unroll
                for (int u = 0; u < 2; u++) {
                    mma_bf16(acc[t][u], ah[t][0], ah[t][1], ah[t][2], ah[t][3], bh[2 * u], bh[2 * u + 1]);
                    mma_bf16(acc[t][u], ah[t][0], ah[t][1], ah[t][2], ah[t][3], bl[2 * u], bl[2 * u + 1]);
                    mma_bf16(acc[t][u], al[t][0], al[t][1], al[t][2], al[t][3], bh[2 * u], bh[2 * u + 1]);
                }
        }
    }

    const int g = lane >> 2;
    const int cpair = (lane & 3) << 1;
    if (POOLG == 0) {
#pragma unroll
        for (int t = 0; t < 2; t++) {
#pragma unroll
            for (int u = 0; u < 2; u++) {
                int col = bn + warp_n * 16 + u * 8 + cpair;
                float v00 = acc[t][u][0], v01 = acc[t][u][1];
                float v10 = acc[t][u][2], v11 = acc[t][u][3];
                if (DOBR) {
                    float b0 = bias[col], b1 = bias[col + 1];
                    v00 = fmaxf(v00 + b0, 0.0f); v01 = fmaxf(v01 + b1, 0.0f);
                    v10 = fmaxf(v10 + b0, 0.0f); v11 = fmaxf(v11 + b1, 0.0f);
                }
                int r0 = bm + warp_m * 32 + t * 16 + g;
                if (OUT_PACKED) {
                    uint32_t* C = (uint32_t*)Cv;
                    *(uint2*)(C + (size_t)r0 * N + col) = make_uint2(packv(v00), packv(v01));
                    *(uint2*)(C + (size_t)(r0 + 8) * N + col) = make_uint2(packv(v10), packv(v11));
                } else {
                    float* C = (float*)Cv;
                    *(float2*)(C + (size_t)r0 * N + col) = make_float2(v00, v01);
                    *(float2*)(C + (size_t)(r0 + 8) * N + col) = make_float2(v10, v11);
                }
            }
        }
    } else {
#pragma unroll
        for (int u = 0; u < 2; u++) {
            int col = bn + warp_n * 16 + u * 8 + cpair;
            float b0 = bias[col], b1 = bias[col + 1];
            float m0 = fmaxf(fmaxf(acc[0][u][0], acc[0][u][2]), fmaxf(acc[1][u][0], acc[1][u][2]));
            float m1 = fmaxf(fmaxf(acc[0][u][1], acc[0][u][3]), fmaxf(acc[1][u][1], acc[1][u][3]));
#pragma unroll
            for (int off = 4; off < 32; off <<= 1) {
                m0 = fmaxf(m0, __shfl_xor_sync(0xffffffffu, m0, off));
                m1 = fmaxf(m1, __shfl_xor_sync(0xffffffffu, m1, off));
            }
            m0 = fmaxf(m0 + b0, 0.0f);
            m1 = fmaxf(m1 + b1, 0.0f);
            if (lane < 4) {
                int lc = warp_n * 16 + u * 8 + cpair;
                pool[warp_m][lc] = m0;
                pool[warp_m][lc + 1] = m1;
            }
        }
        __syncthreads();
        if (tid < 64) {
            float v = fmaxf(fmaxf(pool[0][tid], pool[1][tid]),
                            fmaxf(pool[2][tid], pool[3][tid]));
            ((float*)Cv)[(size_t)(bm / POOLG) * N + bn + tid] = v;
        }
    }
}

// ---------------- REDUX argmax helper: max dist (bits), tie -> min index ------
__device__ __forceinline__ void redux_argmax(float bestv, int besti,
                                             unsigned& mxbits, int& widx) {
    unsigned b = __float_as_uint(bestv);
    mxbits = __reduce_max_sync(0xffffffffu, b);
    int cand = (b == mxbits) ? besti : 0x7fffffff;
    widx = __reduce_min_sync(0xffffffffu, cand);
}

// ---------------- FPS level 1: 512 threads, PPT=8, REDUX reduce ----------------
__global__ void fps_kernel(const float* __restrict__ pts, int S,
                           int* __restrict__ outIdx, float* __restrict__ outXyz) {
    const int T = 512;
    const int PPT = 8;
    int b = blockIdx.x;
    int t = threadIdx.x;
    const float* base = pts + (size_t)b * 3 * N1;

    __shared__ float sxp[4096], syp[4096], szp[4096];
    __shared__ float s_c[3];
    __shared__ float s_v[16];
    __shared__ int   s_i[16];

    float px[PPT], py[PPT], pz[PPT], dist[PPT];
#pragma unroll
    for (int j = 0; j < PPT; j++) {
        int i = t + j * T;
        px[j] = base[i];
        py[j] = base[N1 + i];
        pz[j] = base[2 * N1 + i];
        dist[j] = 1e10f;
        sxp[i] = px[j]; syp[i] = py[j]; szp[i] = pz[j];
    }

    if (t == 0) {
        outIdx[(size_t)b * S] = 0;
        float* ox = outXyz + ((size_t)b * S) * 3;
        s_c[0] = sxp[0]; s_c[1] = syp[0]; s_c[2] = szp[0];
        ox[0] = s_c[0]; ox[1] = s_c[1]; ox[2] = s_c[2];
    }
    __syncthreads();

    for (int it = 0; it < S - 1; it++) {
        float cx = s_c[0], cy = s_c[1], cz = s_c[2];
        float bestv; int besti;
        {
            float d = sqd(px[0] - cx, py[0] - cy, pz[0] - cz);
            dist[0] = fminf(dist[0], d);
            bestv = dist[0]; besti = t;
        }
#pragma unroll
        for (int j = 1; j < PPT; j++) {
            float d = sqd(px[j] - cx, py[j] - cy, pz[j] - cz);
            float nd = fminf(dist[j], d);
            dist[j] = nd;
            if (nd > bestv) { bestv = nd; besti = t + j * T; }
        }
        unsigned mx; int wi;
        redux_argmax(bestv, besti, mx, wi);
        if ((t & 31) == 0) { s_v[t >> 5] = __uint_as_float(mx); s_i[t >> 5] = wi; }
        __syncthreads();
        if (t < 32) {
            float v = (t < 16) ? s_v[t] : 0.0f;
            int   ii = (t < 16) ? s_i[t] : 0x7fffffff;
            redux_argmax(v, ii, mx, wi);
            if (t == 0) {
                float nx = sxp[wi], ny = syp[wi], nz = szp[wi];
                s_c[0] = nx; s_c[1] = ny; s_c[2] = nz;
                outIdx[(size_t)b * S + it + 1] = wi;
                float* ox = outXyz + ((size_t)b * S + it + 1) * 3;
                ox[0] = nx; ox[1] = ny; ox[2] = nz;
            }
        }
        __syncthreads();
    }
}

// ---------------- FPS level 2: one WARP per batch ----------------
__global__ void fps_warp(const float* __restrict__ pts, int S,
                         int* __restrict__ outIdx, float* __restrict__ outXyz) {
    const int PPT = 16;
    int b = blockIdx.x;
    int lane = threadIdx.x;
    const float* base = pts + (size_t)b * 512 * 3;

    __shared__ float sx[512], sy[512], sz[512];
    float px[PPT], py[PPT], pz[PPT], dist[PPT];
#pragma unroll
    for (int j = 0; j < PPT; j++) {
        int i = lane + j * 32;
        px[j] = base[i * 3];
        py[j] = base[i * 3 + 1];
        pz[j] = base[i * 3 + 2];
        dist[j] = 1e10f;
        sx[i] = px[j]; sy[i] = py[j]; sz[i] = pz[j];
    }
    __syncwarp();

    float cx = sx[0], cy = sy[0], cz = sz[0];
    if (lane == 0) {
        outIdx[(size_t)b * S] = 0;
        float* ox = outXyz + ((size_t)b * S) * 3;
        ox[0] = cx; ox[1] = cy; ox[2] = cz;
    }

    for (int it = 0; it < S - 1; it++) {
        float bestv; int besti;
        {
            float d = sqd(px[0] - cx, py[0] - cy, pz[0] - cz);
            dist[0] = fminf(dist[0], d);
            bestv = dist[0]; besti = lane;
        }
#pragma unroll
        for (int j = 1; j < PPT; j++) {
            float d = sqd(px[j] - cx, py[j] - cy, pz[j] - cz);
            float nd = fminf(dist[j], d);
            dist[j] = nd;
            if (nd > bestv) { bestv = nd; besti = lane + j * 32; }
        }
        unsigned mx; int wi;
        redux_argmax(bestv, besti, mx, wi);
        cx = sx[wi]; cy = sy[wi]; cz = sz[wi];
        if (lane == 0) {
            outIdx[(size_t)b * S + it + 1] = wi;
            float* ox = outXyz + ((size_t)b * S + it + 1) * 3;
            ox[0] = cx; ox[1] = cy; ox[2] = cz;
        }
    }
}

// ---------------- ball query + grouping, SA1 ----------------
__global__ void bq_group1(const float* __restrict__ xyz,
                          const float* __restrict__ cent,
                          float* __restrict__ out) {
    extern __shared__ float sm[];
    float* sx = sm; float* sy = sm + N1; float* sz = sm + 2 * N1;
    __shared__ int sel[8][G1];
    int b = blockIdx.x;
    const float* base = xyz + (size_t)b * 3 * N1;
    for (int i = threadIdx.x; i < N1; i += blockDim.x) {
        sx[i] = base[i]; sy[i] = base[N1 + i]; sz[i] = base[2 * N1 + i];
    }
    __syncthreads();
    const float R2 = (float)(0.2 * 0.2);
    int warp = threadIdx.x >> 5, lane = threadIdx.x & 31;
    for (int s = blockIdx.y * 8 + warp; s < S1; s += gridDim.y * 8) {
        const float* cc = cent + ((size_t)b * S1 + s) * 3;
        float cx = cc[0], cy = cc[1], cz = cc[2];
        int cnt = 0, first = -1;
        for (int bi = 0; bi < N1; bi += 32) {
            int i = bi + lane;
            float d = sqd(sx[i] - cx, sy[i] - cy, sz[i] - cz);
            bool ok = (d <= R2);
            unsigned m = __ballot_sync(0xffffffffu, ok);
            if (m) {
                if (first < 0) first = bi + __ffs(m) - 1;
                int pos = cnt + __popc(m & ((1u << lane) - 1u));
                if (ok && pos < G1) sel[warp][pos] = i;
                cnt += __popc(m);
                if (cnt >= G1) break;
            }
        }
        for (int p = cnt + lane; p < G1; p += 32) sel[warp][p] = first;
        __syncwarp();
        int i = sel[warp][lane];
        size_t row = (((size_t)(b * S1 + s)) * G1 + lane) * 3;
        out[row + 0] = sx[i] - cx;
        out[row + 1] = sy[i] - cy;
        out[row + 2] = sz[i] - cz;
        __syncwarp();
    }
}

// ---------------- ball query SA2: indices only ----------------
__global__ void bq_group2_idx(const float* __restrict__ pts,
                              const float* __restrict__ cent,
                              int* __restrict__ gidx) {
    __shared__ float sx[512], sy[512], sz[512];
    __shared__ int sel[8][G2];
    int b = blockIdx.x;
    const float* base = pts + (size_t)b * 512 * 3;
    for (int i = threadIdx.x; i < 512; i += blockDim.x) {
        sx[i] = base[i * 3]; sy[i] = base[i * 3 + 1]; sz[i] = base[i * 3 + 2];
    }
    __syncthreads();
    const float R2 = (float)(0.4 * 0.4);
    int warp = threadIdx.x >> 5, lane = threadIdx.x & 31;
    for (int s = blockIdx.y * 8 + warp; s < S2; s += gridDim.y * 8) {
        const float* cc = cent + ((size_t)b * S2 + s) * 3;
        float cx = cc[0], cy = cc[1], cz = cc[2];
        int cnt = 0, first = -1;
        for (int bi = 0; bi < 512; bi += 32) {
            int i = bi + lane;
            float d = sqd(sx[i] - cx, sy[i] - cy, sz[i] - cz);
            bool ok = (d <= R2);
            unsigned m = __ballot_sync(0xffffffffu, ok);
            if (m) {
                if (first < 0) first = bi + __ffs(m) - 1;
                int pos = cnt + __popc(m & ((1u << lane) - 1u));
                if (ok && pos < G2) sel[warp][pos] = i;
                cnt += __popc(m);
                if (cnt >= G2) break;
            }
        }
        for (int p = cnt + lane; p < G2; p += 32) sel[warp][p] = first;
        __syncwarp();
        int* dst = gidx + (size_t)(b * S2 + s) * G2;
        dst[lane] = sel[warp][lane];
        dst[lane + 32] = sel[warp][lane + 32];
        __syncwarp();
    }
}

// ---------------- generic fp32 GEMM (small head layers, M=32) ----------------
#define BM 128
#define BN 64
#define BK 16
__global__ void gemm_bias_act(const float* __restrict__ A, const float* __restrict__ W,
                              const float* __restrict__ bias, float* __restrict__ C,
                              int M, int K, int N, int doRelu) {
    __shared__ float As[BK][BM + 4];
    __shared__ float Ws[BK][BN];
    int bm = blockIdx.x * BM, bn = blockIdx.y * BN;
    int tid = threadIdx.x;
    int tx = tid & 15, ty = tid >> 4;
    float acc[8][4] = {};

    for (int k0 = 0; k0 < K; k0 += BK) {
        int lr = tid >> 1, lk0 = (tid & 1) * 8;
        int gm = bm + lr;
#pragma unroll
        for (int i = 0; i < 8; i++) {
            int kk = k0 + lk0 + i;
            As[lk0 + i][lr] = (gm < M && kk < K) ? A[(size_t)gm * K + kk] : 0.0f;
        }
        int ln = tid >> 2, lkw = (tid & 3) * 4;
        int gn = bn + ln;
#pragma unroll
        for (int i = 0; i < 4; i++) {
            int kk = k0 + lkw + i;
            Ws[lkw + i][ln] = (gn < N && kk < K) ? W[(size_t)gn * K + kk] : 0.0f;
        }
        __syncthreads();
#pragma unroll
        for (int k = 0; k < BK; k++) {
            float a[8], bvv[4];
#pragma unroll
            for (int i = 0; i < 8; i++) a[i] = As[k][ty * 8 + i];
#pragma unroll
            for (int j = 0; j < 4; j++) bvv[j] = Ws[k][tx * 4 + j];
#pragma unroll
            for (int i = 0; i < 8; i++)
#pragma unroll
                for (int j = 0; j < 4; j++) acc[i][j] += a[i] * bvv[j];
        }
        __syncthreads();
    }
#pragma unroll
    for (int j = 0; j < 4; j++) {
        int gn = bn + tx * 4 + j;
        if (gn >= N) continue;
        float bv = bias[gn];
#pragma unroll
        for (int i = 0; i < 8; i++) {
            int gm = bm + ty * 8 + i;
            if (gm < M) {
                float v = acc[i][j] + bv;
                if (doRelu) v = fmaxf(v, 0.0f);
                C[(size_t)gm * N + gn] = v;
            }
        }
    }
}

// ---------------- SA3 concat (PACKED, stride 288) ----------------
__global__ void concat_sa3(const float* __restrict__ cent2, const uint32_t* __restrict__ l2p,
                           uint32_t* __restrict__ out) {
    int idx = blockIdx.x * blockDim.x + threadIdx.x;
    const int TOT = BATCH * S2 * 288;
    if (idx >= TOT) return;
    int r = idx / 288, c = idx - r * 288;
    uint32_t v;
    if (c < 3) v = packv(cent2[r * 3 + c]);
    else if (c < 259) v = l2p[(size_t)r * 256 + (c - 3)];
    else v = 0;
    out[idx] = v;
}

// ---------------- orchestration ----------------
static inline void launch_gemm_simt(const float* A, const float* W, const float* bias, float* C,
                                    int M, int K, int N, int relu) {
    dim3 grid((M + BM - 1) / BM, (N + BN - 1) / BN);
    gemm_bias_act<<<grid, 256>>>(A, W, bias, C, M, K, N, relu);
}

extern "C" void kernel_launch(void* const* d_in, const int* in_sizes, int n_in,
                              void* d_out, int out_size) {
    (void)in_sizes; (void)n_in; (void)out_size;
    const float* xyz  = (const float*)d_in[0];
    const float* s1w0 = (const float*)d_in[1];  const float* s1b0 = (const float*)d_in[2];
    const float* s1w1 = (const float*)d_in[3];  const float* s1b1 = (const float*)d_in[4];
    const float* s1w2 = (const float*)d_in[5];  const float* s1b2 = (const float*)d_in[6];
    const float* s2w0 = (const float*)d_in[7];  const float* s2b0 = (const float*)d_in[8];
    const float* s2w1 = (const float*)d_in[9];  const float* s2b1 = (const float*)d_in[10];
    const float* s2w2 = (const float*)d_in[11]; const float* s2b2 = (const float*)d_in[12];
    const float* s3w0 = (const float*)d_in[13]; const float* s3b0 = (const float*)d_in[14];
    const float* s3w1 = (const float*)d_in[15]; const float* s3b1 = (const float*)d_in[16];
    const float* s3w2 = (const float*)d_in[17]; const float* s3b2 = (const float*)d_in[18];
    const float* f1w  = (const float*)d_in[19]; const float* f1b  = (const float*)d_in[20];
    const float* f2w  = (const float*)d_in[21]; const float* f2b  = (const float*)d_in[22];
    const float* f3w  = (const float*)d_in[23]; const float* f3b  = (const float*)d_in[24];
    float* out = (float*)d_out;

    float *bufA, *bufB, *cent1, *cent2, *l1p, *l2p, *featv;
    int *idx1, *gidx2;
    uint32_t* wpk;
    cudaGetSymbolAddress((void**)&bufA, g_bufA);
    cudaGetSymbolAddress((void**)&bufB, g_bufB);
    cudaGetSymbolAddress((void**)&cent1, g_cent1);
    cudaGetSymbolAddress((void**)&cent2, g_cent2);
    cudaGetSymbolAddress((void**)&l1p, g_l1p);
    cudaGetSymbolAddress((void**)&l2p, g_l2p);
    cudaGetSymbolAddress((void**)&featv, g_feat);
    cudaGetSymbolAddress((void**)&idx1, g_idx1);
    cudaGetSymbolAddress((void**)&gidx2, g_gidx2);
    cudaGetSymbolAddress((void**)&wpk, g_wpk);
    uint32_t* bufA_u = (uint32_t*)bufA;
    uint32_t* bufB_u = (uint32_t*)bufB;
    uint32_t* l1p_u = (uint32_t*)l1p;
    uint32_t* l2p_u = (uint32_t*)l2p;
    float* FP = bufB + FP_OFFSET;   // 16384 x 128 fp32

    cudaFuncSetAttribute(bq_group1, cudaFuncAttributeMaxDynamicSharedMemorySize, 3 * N1 * 4);
    cudaFuncSetAttribute(sa1_fused, cudaFuncAttributeMaxDynamicSharedMemorySize, SA1_SMEM);
    cudaFuncSetAttribute(sa2_fused, cudaFuncAttributeMaxDynamicSharedMemorySize, SA2_SMEM);

    const int M1 = BATCH * S1 * G1;   // 524288

    // ---- single merged weight pre-pack ----
    {
        PkTab tab;
        auto seg = [&](int i, const float* src, int dst, int N, int Kcopy, int Kp,
                       int srcK, int colOff) {
            tab.s[i].src = src; tab.s[i].dst = dst; tab.s[i].Kp = Kp;
            tab.s[i].srcK = srcK; tab.s[i].colOff = colOff; tab.s[i].Kcopy = Kcopy;
            tab.cum[i + 1] = tab.cum[i] + N * Kp;
        };
        tab.cum[0] = 0;
        seg(0, s1w1, WO_S1W1, 64, 64, 64, 64, 0);
        seg(1, s1w2, WO_S1W2, 128, 64, 64, 64, 0);
        seg(2, s2w1, WO_S2W1, 128, 128, 128, 128, 0);
        seg(3, s2w2, WO_S2W2, 256, 128, 128, 128, 0);
        seg(4, s3w0, WO_S3W0, 256, 259, 288, 259, 0);
        seg(5, s3w1, WO_S3W1, 512, 256, 256, 256, 0);
        seg(6, s3w2, WO_S3W2, 1024, 512, 512, 512, 0);
        seg(7, s2w0, WO_FPW, 128, 128, 128, 131, 3);   // feat cols 3..130
        prepack_all<<<(tab.cum[8] + 255) / 256, 256>>>(tab, wpk);
    }

    // ---- SA1 ----
    fps_kernel<<<BATCH, 512>>>(xyz, S1, idx1, cent1);
    bq_group1<<<dim3(BATCH, 8), 256, 3 * N1 * 4>>>(xyz, cent1, bufA);
    sa1_fused<<<M1 / 128, 512, SA1_SMEM>>>(bufA, s1w0, s1b0,
                                           wpk + WO_S1W1, s1b1, wpk + WO_S1W2, s1b2, l1p_u);

    // ---- feature projection of unique points (dedups SA2 L1) ----
    gemm_str<0, 0, 0><<<dim3(128, 2), 512>>>(l1p_u, wpk + WO_FPW, nullptr, FP,
                                             16384, 128, 128, 128);

    // ---- SA2 ----
    fps_warp<<<BATCH, 32>>>(cent1, S2, idx1, cent2);
    bq_group2_idx<<<dim3(BATCH, 2), 256>>>(cent1, cent2, gidx2);
    sa2_fused<<<(BATCH * S2 * G2) / 128, 512, SA2_SMEM>>>(
        gidx2, cent1, cent2, FP, s2w0, s2b0,
        wpk + WO_S2W1, s2b1, wpk + WO_S2W2, s2b2, l2p_u);

    // ---- SA3 (group all; M=4096, streaming) ----
    concat_sa3<<<(BATCH * S2 * 288 + 255) / 256, 256>>>(cent2, l2p_u, bufB_u);
    gemm_str<0, 1, 1><<<dim3(32, 4), 512>>>(bufB_u, wpk + WO_S3W0, s3b0, bufA_u, 4096, 288, 288, 256);
    gemm_str<0, 1, 1><<<dim3(32, 8), 512>>>(bufA_u, wpk + WO_S3W1, s3b1, bufB_u, 4096, 256, 256, 512);
    gemm_str<128, 0, 1><<<dim3(32, 16), 512>>>(bufB_u, wpk + WO_S3W2, s3b2, featv, 4096, 512, 512, 1024);

    // ---- head (tiny, fp32) ----
    launch_gemm_simt(featv, f1w, f1b, bufA, BATCH, 1024, 512, 1);
    launch_gemm_simt(bufA, f2w, f2b, bufB, BATCH, 512, 256, 1);
    launch_gemm_simt(bufB, f3w, f3b, out, BATCH, 256, 6, 0);
}